// round 1
// baseline (speedup 1.0000x reference)
#include <cuda_runtime.h>
#include <cuda_bf16.h>
#include <math.h>

// ---------------------------------------------------------------------------
// ViT block, fp32 baseline.
//   qkv = x @ qkv_w + qkv_b
//   flash-attention per (b,h), DH=64
//   a  = att @ proj_w + proj_b
//   y1 = a + LN(a; n1)
//   h1 = GELU(y1 @ fc1_w + fc1_b)   (exact erf gelu)
//   h2 = h1 @ fc2_w + fc2_b
//   out = y1 + LN(h2; n2)
// ---------------------------------------------------------------------------

#define Bq   8
#define Nq   1024
#define Cq   1024
#define Hq   16
#define DHq  64
#define Mrows (Bq*Nq)          // 8192
#define SCALE 0.125f           // DH^-0.5
#define EPSLN 1e-6f

// Scratch (static device memory; allocation APIs are forbidden)
__device__ float g_qkv[Mrows * 3 * Cq];   // 96 MB
__device__ float g_att[Mrows * Cq];       // 32 MB
__device__ float g_a  [Mrows * Cq];       // 32 MB
__device__ float g_y1 [Mrows * Cq];       // 32 MB
__device__ float g_h1 [Mrows * 4 * Cq];   // 128 MB
__device__ float g_h2 [Mrows * Cq];       // 32 MB

// ---------------------------------------------------------------------------
// GEMM: C[M,N] = A[M,K] @ B[K,N] + bias[N], optional exact GELU.
// 128x128 block tile, K-tile 16, 256 threads, 8x8 register tile per thread.
// ---------------------------------------------------------------------------
__global__ __launch_bounds__(256, 2) void gemm_bias_kernel(
    const float* __restrict__ A, const float* __restrict__ B,
    const float* __restrict__ bias, float* __restrict__ C,
    int M, int N, int K, int gelu)
{
    __shared__ float As[16][132];   // transposed A tile [k][m], padded
    __shared__ float Bs[16][128];   // B tile [k][n]

    const int tid = threadIdx.x;
    const int bm = blockIdx.y * 128;
    const int bn = blockIdx.x * 128;
    const int ty = tid >> 4;        // 0..15
    const int tx = tid & 15;        // 0..15

    float acc[8][8];
#pragma unroll
    for (int i = 0; i < 8; i++)
#pragma unroll
        for (int j = 0; j < 8; j++) acc[i][j] = 0.f;

    for (int k0 = 0; k0 < K; k0 += 16) {
        // load A tile (128 rows x 16 cols) transposed into As
#pragma unroll
        for (int i = 0; i < 2; i++) {
            int idx = tid + i * 256;          // 0..511
            int r = idx >> 2;                 // 0..127
            int c = (idx & 3) << 2;           // 0,4,8,12
            float4 v = *(const float4*)&A[(size_t)(bm + r) * K + k0 + c];
            As[c + 0][r] = v.x;
            As[c + 1][r] = v.y;
            As[c + 2][r] = v.z;
            As[c + 3][r] = v.w;
        }
        // load B tile (16 rows x 128 cols)
#pragma unroll
        for (int i = 0; i < 2; i++) {
            int idx = tid + i * 256;
            int r = idx >> 5;                 // 0..15
            int c = (idx & 31) << 2;          // 0..124
            *(float4*)&Bs[r][c] = *(const float4*)&B[(size_t)(k0 + r) * N + bn + c];
        }
        __syncthreads();

#pragma unroll
        for (int kk = 0; kk < 16; kk++) {
            float a[8], b[8];
            *(float4*)&a[0] = *(float4*)&As[kk][ty * 8];
            *(float4*)&a[4] = *(float4*)&As[kk][ty * 8 + 4];
            *(float4*)&b[0] = *(float4*)&Bs[kk][tx * 8];
            *(float4*)&b[4] = *(float4*)&Bs[kk][tx * 8 + 4];
#pragma unroll
            for (int i = 0; i < 8; i++)
#pragma unroll
                for (int j = 0; j < 8; j++)
                    acc[i][j] += a[i] * b[j];
        }
        __syncthreads();
    }

    // epilogue: bias (+ optional exact gelu), float4 stores
#pragma unroll
    for (int i = 0; i < 8; i++) {
        int row = bm + ty * 8 + i;
#pragma unroll
        for (int j4 = 0; j4 < 2; j4++) {
            int col = bn + tx * 8 + j4 * 4;
            float4 bv = *(const float4*)&bias[col];
            float4 o;
            o.x = acc[i][j4 * 4 + 0] + bv.x;
            o.y = acc[i][j4 * 4 + 1] + bv.y;
            o.z = acc[i][j4 * 4 + 2] + bv.z;
            o.w = acc[i][j4 * 4 + 3] + bv.w;
            if (gelu) {
                o.x = 0.5f * o.x * (1.f + erff(o.x * 0.70710678118654752f));
                o.y = 0.5f * o.y * (1.f + erff(o.y * 0.70710678118654752f));
                o.z = 0.5f * o.z * (1.f + erff(o.z * 0.70710678118654752f));
                o.w = 0.5f * o.w * (1.f + erff(o.w * 0.70710678118654752f));
            }
            *(float4*)&C[(size_t)row * N + col] = o;
        }
    }
}

// ---------------------------------------------------------------------------
// Flash attention. grid = (N/64, B*H); 256 threads; 64-row Q tile, 64-row K/V
// tiles, online softmax. Q pre-scaled by SCALE. Output written to [B,N,C].
// ---------------------------------------------------------------------------
#define QS_STRIDE 65
#define KT_STRIDE 65
#define VS_STRIDE 68
#define PS_STRIDE 65
#define ATT_SMEM_FLOATS (64*QS_STRIDE + 64*KT_STRIDE + 64*VS_STRIDE + 64*PS_STRIDE)

__global__ __launch_bounds__(256, 2) void attn_kernel(
    const float* __restrict__ qkv, float* __restrict__ out)
{
    extern __shared__ float sm[];
    float* Qs = sm;                      // [r][d]  stride 65
    float* Kt = Qs + 64 * QS_STRIDE;     // [d][r]  stride 65  (transposed K)
    float* Vs = Kt + 64 * KT_STRIDE;     // [r][d]  stride 68
    float* Ps = Vs + 64 * VS_STRIDE;     // [r][k]  stride 65

    const int bh = blockIdx.y;
    const int b = bh >> 4;
    const int h = bh & 15;
    const int q0 = blockIdx.x * 64;
    const int tid = threadIdx.x;
    const int ty = tid >> 4;   // 0..15 -> rows ty*4..ty*4+3
    const int tx = tid & 15;   // 0..15 -> cols tx*4..tx*4+3

    const size_t base = (size_t)b * Nq * (3 * Cq);

    // load Q tile, pre-scaled
#pragma unroll
    for (int i = 0; i < 4; i++) {
        int idx = tid + i * 256;       // 0..1023
        int r = idx >> 4;              // 0..63
        int c = (idx & 15) << 2;       // 0..60
        float4 v = *(const float4*)&qkv[base + (size_t)(q0 + r) * (3 * Cq) + h * 64 + c];
        Qs[r * QS_STRIDE + c + 0] = v.x * SCALE;
        Qs[r * QS_STRIDE + c + 1] = v.y * SCALE;
        Qs[r * QS_STRIDE + c + 2] = v.z * SCALE;
        Qs[r * QS_STRIDE + c + 3] = v.w * SCALE;
    }

    float m_i[4], l_i[4], o[4][4];
#pragma unroll
    for (int i = 0; i < 4; i++) {
        m_i[i] = -INFINITY; l_i[i] = 0.f;
#pragma unroll
        for (int j = 0; j < 4; j++) o[i][j] = 0.f;
    }

    for (int kt = 0; kt < Nq; kt += 64) {
        __syncthreads();   // previous iter's Ps/Vs reads done before overwrite
        // load K (store transposed) and V
#pragma unroll
        for (int i = 0; i < 4; i++) {
            int idx = tid + i * 256;
            int r = idx >> 4;
            int c = (idx & 15) << 2;
            float4 kv = *(const float4*)&qkv[base + (size_t)(kt + r) * (3 * Cq) + Cq + h * 64 + c];
            Kt[(c + 0) * KT_STRIDE + r] = kv.x;
            Kt[(c + 1) * KT_STRIDE + r] = kv.y;
            Kt[(c + 2) * KT_STRIDE + r] = kv.z;
            Kt[(c + 3) * KT_STRIDE + r] = kv.w;
            float4 vv = *(const float4*)&qkv[base + (size_t)(kt + r) * (3 * Cq) + 2 * Cq + h * 64 + c];
            *(float4*)&Vs[r * VS_STRIDE + c] = vv;
        }
        __syncthreads();

        // S = Qs @ Kt  (4x4 per thread)
        float s[4][4];
#pragma unroll
        for (int i = 0; i < 4; i++)
#pragma unroll
            for (int j = 0; j < 4; j++) s[i][j] = 0.f;
#pragma unroll 8
        for (int d = 0; d < 64; d++) {
            float qv[4], kv[4];
#pragma unroll
            for (int i = 0; i < 4; i++) qv[i] = Qs[(ty * 4 + i) * QS_STRIDE + d];
#pragma unroll
            for (int j = 0; j < 4; j++) kv[j] = Kt[d * KT_STRIDE + tx * 4 + j];
#pragma unroll
            for (int i = 0; i < 4; i++)
#pragma unroll
                for (int j = 0; j < 4; j++) s[i][j] += qv[i] * kv[j];
        }

        // online softmax update, write P to shared
#pragma unroll
        for (int i = 0; i < 4; i++) {
            float mx = s[i][0];
#pragma unroll
            for (int j = 1; j < 4; j++) mx = fmaxf(mx, s[i][j]);
#pragma unroll
            for (int off = 8; off >= 1; off >>= 1)
                mx = fmaxf(mx, __shfl_xor_sync(0xffffffffu, mx, off, 16));
            float mnew = fmaxf(m_i[i], mx);
            float rs = 0.f;
            float p[4];
#pragma unroll
            for (int j = 0; j < 4; j++) { p[j] = __expf(s[i][j] - mnew); rs += p[j]; }
#pragma unroll
            for (int off = 8; off >= 1; off >>= 1)
                rs += __shfl_xor_sync(0xffffffffu, rs, off, 16);
            float corr = __expf(m_i[i] - mnew);
            l_i[i] = l_i[i] * corr + rs;
            m_i[i] = mnew;
#pragma unroll
            for (int j = 0; j < 4; j++) {
                o[i][j] *= corr;
                Ps[(ty * 4 + i) * PS_STRIDE + tx * 4 + j] = p[j];
            }
        }
        __syncthreads();

        // O += P @ V
#pragma unroll 8
        for (int kk = 0; kk < 64; kk++) {
            float pv[4], vv[4];
#pragma unroll
            for (int i = 0; i < 4; i++) pv[i] = Ps[(ty * 4 + i) * PS_STRIDE + kk];
#pragma unroll
            for (int j = 0; j < 4; j++) vv[j] = Vs[kk * VS_STRIDE + tx * 4 + j];
#pragma unroll
            for (int i = 0; i < 4; i++)
#pragma unroll
                for (int j = 0; j < 4; j++) o[i][j] += pv[i] * vv[j];
        }
    }

    // write output rows q0+ty*4+i, cols h*64 + tx*4+j
#pragma unroll
    for (int i = 0; i < 4; i++) {
        float inv = 1.f / l_i[i];
        size_t row = (size_t)b * Nq + q0 + ty * 4 + i;
#pragma unroll
        for (int j = 0; j < 4; j++)
            out[row * Cq + h * 64 + tx * 4 + j] = o[i][j] * inv;
    }
}

// ---------------------------------------------------------------------------
// out[row] = res[row] + LayerNorm(in[row]) * g + b      (rows of 1024)
// grid = 8192 blocks, 256 threads, 4 elems/thread.
// ---------------------------------------------------------------------------
__global__ __launch_bounds__(256) void ln_add_kernel(
    const float* __restrict__ in, const float* __restrict__ res,
    const float* __restrict__ g, const float* __restrict__ bt,
    float* __restrict__ out)
{
    const int row = blockIdx.x;
    const int tid = threadIdx.x;
    const size_t off = (size_t)row * Cq + tid * 4;

    float4 v = *(const float4*)&in[off];
    float s = v.x + v.y + v.z + v.w;
    float ss = v.x * v.x + v.y * v.y + v.z * v.z + v.w * v.w;

#pragma unroll
    for (int o2 = 16; o2 > 0; o2 >>= 1) {
        s  += __shfl_xor_sync(0xffffffffu, s,  o2);
        ss += __shfl_xor_sync(0xffffffffu, ss, o2);
    }
    __shared__ float sh_s[8], sh_ss[8], red[2];
    if ((tid & 31) == 0) { sh_s[tid >> 5] = s; sh_ss[tid >> 5] = ss; }
    __syncthreads();
    if (tid < 32) {
        float a  = (tid < 8) ? sh_s[tid]  : 0.f;
        float a2 = (tid < 8) ? sh_ss[tid] : 0.f;
#pragma unroll
        for (int o2 = 4; o2 > 0; o2 >>= 1) {
            a  += __shfl_xor_sync(0xffffffffu, a,  o2);
            a2 += __shfl_xor_sync(0xffffffffu, a2, o2);
        }
        if (tid == 0) {
            float mean = a * (1.f / Cq);
            float var = a2 * (1.f / Cq) - mean * mean;
            red[0] = mean;
            red[1] = rsqrtf(var + EPSLN);
        }
    }
    __syncthreads();
    float mean = red[0], inv = red[1];

    float4 gv = *(const float4*)&g[tid * 4];
    float4 bv = *(const float4*)&bt[tid * 4];
    float4 rv = *(const float4*)&res[off];
    float4 o;
    o.x = rv.x + (v.x - mean) * inv * gv.x + bv.x;
    o.y = rv.y + (v.y - mean) * inv * gv.y + bv.y;
    o.z = rv.z + (v.z - mean) * inv * gv.z + bv.z;
    o.w = rv.w + (v.w - mean) * inv * gv.w + bv.w;
    *(float4*)&out[off] = o;
}

// ---------------------------------------------------------------------------
// host launcher
// ---------------------------------------------------------------------------
extern "C" void kernel_launch(void* const* d_in, const int* in_sizes, int n_in,
                              void* d_out, int out_size)
{
    const float* x      = (const float*)d_in[0];
    const float* qkv_w  = (const float*)d_in[1];
    const float* qkv_b  = (const float*)d_in[2];
    const float* proj_w = (const float*)d_in[3];
    const float* proj_b = (const float*)d_in[4];
    const float* n1_g   = (const float*)d_in[5];
    const float* n1_b   = (const float*)d_in[6];
    const float* fc1_w  = (const float*)d_in[7];
    const float* fc1_b  = (const float*)d_in[8];
    const float* fc2_w  = (const float*)d_in[9];
    const float* fc2_b  = (const float*)d_in[10];
    const float* n2_g   = (const float*)d_in[11];
    const float* n2_b   = (const float*)d_in[12];
    float* out = (float*)d_out;

    float *p_qkv, *p_att, *p_a, *p_y1, *p_h1, *p_h2;
    cudaGetSymbolAddress((void**)&p_qkv, g_qkv);
    cudaGetSymbolAddress((void**)&p_att, g_att);
    cudaGetSymbolAddress((void**)&p_a,   g_a);
    cudaGetSymbolAddress((void**)&p_y1,  g_y1);
    cudaGetSymbolAddress((void**)&p_h1,  g_h1);
    cudaGetSymbolAddress((void**)&p_h2,  g_h2);

    static int attn_smem_set = 0;
    (void)attn_smem_set;
    cudaFuncSetAttribute(attn_kernel, cudaFuncAttributeMaxDynamicSharedMemorySize,
                         ATT_SMEM_FLOATS * sizeof(float));

    // 1) qkv = x @ qkv_w + qkv_b          [8192,1024] x [1024,3072]
    gemm_bias_kernel<<<dim3(3 * Cq / 128, Mrows / 128), 256>>>(
        x, qkv_w, qkv_b, p_qkv, Mrows, 3 * Cq, Cq, 0);

    // 2) attention -> p_att [8192,1024]
    attn_kernel<<<dim3(Nq / 64, Bq * Hq), 256, ATT_SMEM_FLOATS * sizeof(float)>>>(
        p_qkv, p_att);

    // 3) a = att @ proj_w + proj_b
    gemm_bias_kernel<<<dim3(Cq / 128, Mrows / 128), 256>>>(
        p_att, proj_w, proj_b, p_a, Mrows, Cq, Cq, 0);

    // 4) y1 = a + LN(a)
    ln_add_kernel<<<Mrows, 256>>>(p_a, p_a, n1_g, n1_b, p_y1);

    // 5) h1 = GELU(y1 @ fc1_w + fc1_b)    [8192,1024] x [1024,4096]
    gemm_bias_kernel<<<dim3(4 * Cq / 128, Mrows / 128), 256>>>(
        p_y1, fc1_w, fc1_b, p_h1, Mrows, 4 * Cq, Cq, 1);

    // 6) h2 = h1 @ fc2_w + fc2_b          [8192,4096] x [4096,1024]
    gemm_bias_kernel<<<dim3(Cq / 128, Mrows / 128), 256>>>(
        p_h1, fc2_w, fc2_b, p_h2, Mrows, Cq, 4 * Cq, 0);

    // 7) out = y1 + LN(h2)
    ln_add_kernel<<<Mrows, 256>>>(p_h2, p_y1, n2_g, n2_b, out);
}

// round 3
// speedup vs baseline: 2.0763x; 2.0763x over previous
#include <cuda_runtime.h>
#include <cuda_bf16.h>
#include <math.h>
#include <stdint.h>

// ---------------------------------------------------------------------------
// ViT block. GEMMs on tensor cores (tf32 mma.sync, fp32 accum), flash
// attention + LN in fp32.
//   qkv = x @ qkv_w + qkv_b
//   flash-attention per (b,h), DH=64
//   a  = att @ proj_w + proj_b
//   y1 = a + LN(a; n1)
//   h1 = GELU(y1 @ fc1_w + fc1_b)
//   h2 = h1 @ fc2_w + fc2_b
//   out = y1 + LN(h2; n2)
// ---------------------------------------------------------------------------

#define Bq   8
#define Nq   1024
#define Cq   1024
#define Hq   16
#define DHq  64
#define Mrows (Bq*Nq)          // 8192
#define SCALE 0.125f           // DH^-0.5
#define EPSLN 1e-6f

// Scratch (static device memory; allocation APIs are forbidden)
__device__ float g_qkv[Mrows * 3 * Cq];   // 96 MB
__device__ float g_att[Mrows * Cq];       // 32 MB
__device__ float g_a  [Mrows * Cq];       // 32 MB
__device__ float g_y1 [Mrows * Cq];       // 32 MB
__device__ float g_h1 [Mrows * 4 * Cq];   // 128 MB
__device__ float g_h2 [Mrows * Cq];       // 32 MB

__device__ __forceinline__ uint32_t f2tf32(float f) {
    uint32_t u;
    asm("cvt.rna.tf32.f32 %0, %1;" : "=r"(u) : "f"(f));
    return u;
}

#define MMA_TF32(d, a, b)                                                  \
    asm volatile(                                                          \
        "mma.sync.aligned.m16n8k8.row.col.f32.tf32.tf32.f32 "              \
        "{%0,%1,%2,%3}, {%4,%5,%6,%7}, {%8,%9}, {%0,%1,%2,%3};"            \
        : "+f"(d[0]), "+f"(d[1]), "+f"(d[2]), "+f"(d[3])                   \
        : "r"(a[0]), "r"(a[1]), "r"(a[2]), "r"(a[3]), "r"(b[0]), "r"(b[1]))

// ---------------------------------------------------------------------------
// tf32 tensor-core GEMM: C[M,N] = A[M,K] @ B[K,N] + bias[N] (+ exact GELU)
// 128x128 block tile, BK=16, 256 threads (8 warps of 64x32), double buffered.
// M,N multiples of 128; K multiple of 16.
// ---------------------------------------------------------------------------
__global__ __launch_bounds__(256, 2) void gemm_tf32_kernel(
    const float* __restrict__ A, const float* __restrict__ B,
    const float* __restrict__ bias, float* __restrict__ C,
    int M, int N, int K, int gelu)
{
    __shared__ __align__(16) uint32_t As[2][128][20];   // [m][k] pad->20
    __shared__ __align__(16) uint32_t Bs[2][16][136];   // [k][n] pad->136

    const int tid  = threadIdx.x;
    const int lane = tid & 31;
    const int warp = tid >> 5;
    const int gid  = lane >> 2;     // 0..7
    const int tig  = lane & 3;      // 0..3
    const int wm   = (warp >> 2) * 64;   // 0 or 64
    const int wn   = (warp & 3) * 32;    // 0..96
    const int bm   = blockIdx.y * 128;
    const int bn   = blockIdx.x * 128;

    // global-load coordinates (2 float4 per thread for each of A and B)
    const int ar0 = (tid + 0)   >> 2, ac0 = ((tid + 0)   & 3) << 2;
    const int ar1 = (tid + 256) >> 2, ac1 = ((tid + 256) & 3) << 2;
    const int br0 = (tid + 0)   >> 5, bc0 = ((tid + 0)   & 31) << 2;
    const int br1 = (tid + 256) >> 5, bc1 = ((tid + 256) & 31) << 2;

    float acc[4][4][4];
#pragma unroll
    for (int mt = 0; mt < 4; mt++)
#pragma unroll
        for (int nt = 0; nt < 4; nt++)
#pragma unroll
            for (int r = 0; r < 4; r++) acc[mt][nt][r] = 0.f;

    float4 av0, av1, bv0, bv1;

    // prologue: fetch tile 0
    av0 = *(const float4*)&A[(size_t)(bm + ar0) * K + ac0];
    av1 = *(const float4*)&A[(size_t)(bm + ar1) * K + ac1];
    bv0 = *(const float4*)&B[(size_t)br0 * N + bn + bc0];
    bv1 = *(const float4*)&B[(size_t)br1 * N + bn + bc1];
    {
        uint4 u;
        u.x = f2tf32(av0.x); u.y = f2tf32(av0.y); u.z = f2tf32(av0.z); u.w = f2tf32(av0.w);
        *(uint4*)&As[0][ar0][ac0] = u;
        u.x = f2tf32(av1.x); u.y = f2tf32(av1.y); u.z = f2tf32(av1.z); u.w = f2tf32(av1.w);
        *(uint4*)&As[0][ar1][ac1] = u;
        u.x = f2tf32(bv0.x); u.y = f2tf32(bv0.y); u.z = f2tf32(bv0.z); u.w = f2tf32(bv0.w);
        *(uint4*)&Bs[0][br0][bc0] = u;
        u.x = f2tf32(bv1.x); u.y = f2tf32(bv1.y); u.z = f2tf32(bv1.z); u.w = f2tf32(bv1.w);
        *(uint4*)&Bs[0][br1][bc1] = u;
    }
    __syncthreads();

    const int ntiles = K >> 4;
    for (int t = 0; t < ntiles; t++) {
        const int buf = t & 1;
        const int k0g = (t + 1) << 4;
        if (t + 1 < ntiles) {
            av0 = *(const float4*)&A[(size_t)(bm + ar0) * K + k0g + ac0];
            av1 = *(const float4*)&A[(size_t)(bm + ar1) * K + k0g + ac1];
            bv0 = *(const float4*)&B[(size_t)(k0g + br0) * N + bn + bc0];
            bv1 = *(const float4*)&B[(size_t)(k0g + br1) * N + bn + bc1];
        }

        // compute on buf (two k-steps of 8)
#pragma unroll
        for (int ks = 0; ks < 2; ks++) {
            const int k0 = ks * 8;
            uint32_t afr[4][4], bfr[4][2];
#pragma unroll
            for (int mt = 0; mt < 4; mt++) {
                const int m = wm + mt * 16 + gid;
                afr[mt][0] = As[buf][m][k0 + tig];
                afr[mt][1] = As[buf][m + 8][k0 + tig];
                afr[mt][2] = As[buf][m][k0 + tig + 4];
                afr[mt][3] = As[buf][m + 8][k0 + tig + 4];
            }
#pragma unroll
            for (int nt = 0; nt < 4; nt++) {
                const int n = wn + nt * 8 + gid;
                bfr[nt][0] = Bs[buf][k0 + tig][n];
                bfr[nt][1] = Bs[buf][k0 + tig + 4][n];
            }
#pragma unroll
            for (int mt = 0; mt < 4; mt++)
#pragma unroll
                for (int nt = 0; nt < 4; nt++)
                    MMA_TF32(acc[mt][nt], afr[mt], bfr[nt]);
        }

        if (t + 1 < ntiles) {
            const int nb = (t + 1) & 1;
            uint4 u;
            u.x = f2tf32(av0.x); u.y = f2tf32(av0.y); u.z = f2tf32(av0.z); u.w = f2tf32(av0.w);
            *(uint4*)&As[nb][ar0][ac0] = u;
            u.x = f2tf32(av1.x); u.y = f2tf32(av1.y); u.z = f2tf32(av1.z); u.w = f2tf32(av1.w);
            *(uint4*)&As[nb][ar1][ac1] = u;
            u.x = f2tf32(bv0.x); u.y = f2tf32(bv0.y); u.z = f2tf32(bv0.z); u.w = f2tf32(bv0.w);
            *(uint4*)&Bs[nb][br0][bc0] = u;
            u.x = f2tf32(bv1.x); u.y = f2tf32(bv1.y); u.z = f2tf32(bv1.z); u.w = f2tf32(bv1.w);
            *(uint4*)&Bs[nb][br1][bc1] = u;
        }
        __syncthreads();
    }

    // epilogue: bias (+ gelu), float2 stores
#pragma unroll
    for (int mt = 0; mt < 4; mt++) {
        const int row0 = bm + wm + mt * 16 + gid;
#pragma unroll
        for (int nt = 0; nt < 4; nt++) {
            const int col = bn + wn + nt * 8 + tig * 2;
            float2 bv = *(const float2*)&bias[col];
            float c0 = acc[mt][nt][0] + bv.x;
            float c1 = acc[mt][nt][1] + bv.y;
            float c2 = acc[mt][nt][2] + bv.x;
            float c3 = acc[mt][nt][3] + bv.y;
            if (gelu) {
                c0 = 0.5f * c0 * (1.f + erff(c0 * 0.70710678118654752f));
                c1 = 0.5f * c1 * (1.f + erff(c1 * 0.70710678118654752f));
                c2 = 0.5f * c2 * (1.f + erff(c2 * 0.70710678118654752f));
                c3 = 0.5f * c3 * (1.f + erff(c3 * 0.70710678118654752f));
            }
            float2 o01; o01.x = c0; o01.y = c1;
            float2 o23; o23.x = c2; o23.y = c3;
            *(float2*)&C[(size_t)row0 * N + col] = o01;
            *(float2*)&C[(size_t)(row0 + 8) * N + col] = o23;
        }
    }
}

// ---------------------------------------------------------------------------
// Flash attention (fp32 SIMT). grid = (N/64, B*H); 256 threads.
// ---------------------------------------------------------------------------
#define QS_STRIDE 65
#define KT_STRIDE 65
#define VS_STRIDE 68
#define PS_STRIDE 65
#define ATT_SMEM_FLOATS (64*QS_STRIDE + 64*KT_STRIDE + 64*VS_STRIDE + 64*PS_STRIDE)

__global__ __launch_bounds__(256, 2) void attn_kernel(
    const float* __restrict__ qkv, float* __restrict__ out)
{
    extern __shared__ float sm[];
    float* Qs = sm;
    float* Kt = Qs + 64 * QS_STRIDE;
    float* Vs = Kt + 64 * KT_STRIDE;
    float* Ps = Vs + 64 * VS_STRIDE;

    const int bh = blockIdx.y;
    const int b = bh >> 4;
    const int h = bh & 15;
    const int q0 = blockIdx.x * 64;
    const int tid = threadIdx.x;
    const int ty = tid >> 4;
    const int tx = tid & 15;

    const size_t base = (size_t)b * Nq * (3 * Cq);

#pragma unroll
    for (int i = 0; i < 4; i++) {
        int idx = tid + i * 256;
        int r = idx >> 4;
        int c = (idx & 15) << 2;
        float4 v = *(const float4*)&qkv[base + (size_t)(q0 + r) * (3 * Cq) + h * 64 + c];
        Qs[r * QS_STRIDE + c + 0] = v.x * SCALE;
        Qs[r * QS_STRIDE + c + 1] = v.y * SCALE;
        Qs[r * QS_STRIDE + c + 2] = v.z * SCALE;
        Qs[r * QS_STRIDE + c + 3] = v.w * SCALE;
    }

    float m_i[4], l_i[4], o[4][4];
#pragma unroll
    for (int i = 0; i < 4; i++) {
        m_i[i] = -INFINITY; l_i[i] = 0.f;
#pragma unroll
        for (int j = 0; j < 4; j++) o[i][j] = 0.f;
    }

    for (int kt = 0; kt < Nq; kt += 64) {
        __syncthreads();
#pragma unroll
        for (int i = 0; i < 4; i++) {
            int idx = tid + i * 256;
            int r = idx >> 4;
            int c = (idx & 15) << 2;
            float4 kv = *(const float4*)&qkv[base + (size_t)(kt + r) * (3 * Cq) + Cq + h * 64 + c];
            Kt[(c + 0) * KT_STRIDE + r] = kv.x;
            Kt[(c + 1) * KT_STRIDE + r] = kv.y;
            Kt[(c + 2) * KT_STRIDE + r] = kv.z;
            Kt[(c + 3) * KT_STRIDE + r] = kv.w;
            float4 vv = *(const float4*)&qkv[base + (size_t)(kt + r) * (3 * Cq) + 2 * Cq + h * 64 + c];
            *(float4*)&Vs[r * VS_STRIDE + c] = vv;
        }
        __syncthreads();

        float s[4][4];
#pragma unroll
        for (int i = 0; i < 4; i++)
#pragma unroll
            for (int j = 0; j < 4; j++) s[i][j] = 0.f;
#pragma unroll 8
        for (int d = 0; d < 64; d++) {
            float qv[4], kv[4];
#pragma unroll
            for (int i = 0; i < 4; i++) qv[i] = Qs[(ty * 4 + i) * QS_STRIDE + d];
#pragma unroll
            for (int j = 0; j < 4; j++) kv[j] = Kt[d * KT_STRIDE + tx * 4 + j];
#pragma unroll
            for (int i = 0; i < 4; i++)
#pragma unroll
                for (int j = 0; j < 4; j++) s[i][j] += qv[i] * kv[j];
        }

#pragma unroll
        for (int i = 0; i < 4; i++) {
            float mx = s[i][0];
#pragma unroll
            for (int j = 1; j < 4; j++) mx = fmaxf(mx, s[i][j]);
#pragma unroll
            for (int off = 8; off >= 1; off >>= 1)
                mx = fmaxf(mx, __shfl_xor_sync(0xffffffffu, mx, off, 16));
            float mnew = fmaxf(m_i[i], mx);
            float rs = 0.f;
            float p[4];
#pragma unroll
            for (int j = 0; j < 4; j++) { p[j] = __expf(s[i][j] - mnew); rs += p[j]; }
#pragma unroll
            for (int off = 8; off >= 1; off >>= 1)
                rs += __shfl_xor_sync(0xffffffffu, rs, off, 16);
            float corr = __expf(m_i[i] - mnew);
            l_i[i] = l_i[i] * corr + rs;
            m_i[i] = mnew;
#pragma unroll
            for (int j = 0; j < 4; j++) {
                o[i][j] *= corr;
                Ps[(ty * 4 + i) * PS_STRIDE + tx * 4 + j] = p[j];
            }
        }
        __syncthreads();

#pragma unroll 8
        for (int kk = 0; kk < 64; kk++) {
            float pv[4], vv[4];
#pragma unroll
            for (int i = 0; i < 4; i++) pv[i] = Ps[(ty * 4 + i) * PS_STRIDE + kk];
#pragma unroll
            for (int j = 0; j < 4; j++) vv[j] = Vs[kk * VS_STRIDE + tx * 4 + j];
#pragma unroll
            for (int i = 0; i < 4; i++)
#pragma unroll
                for (int j = 0; j < 4; j++) o[i][j] += pv[i] * vv[j];
        }
    }

#pragma unroll
    for (int i = 0; i < 4; i++) {
        float inv = 1.f / l_i[i];
        size_t row = (size_t)b * Nq + q0 + ty * 4 + i;
#pragma unroll
        for (int j = 0; j < 4; j++)
            out[row * Cq + h * 64 + tx * 4 + j] = o[i][j] * inv;
    }
}

// ---------------------------------------------------------------------------
// out[row] = res[row] + LayerNorm(in[row]) * g + b      (rows of 1024)
// ---------------------------------------------------------------------------
__global__ __launch_bounds__(256) void ln_add_kernel(
    const float* __restrict__ in, const float* __restrict__ res,
    const float* __restrict__ g, const float* __restrict__ bt,
    float* __restrict__ out)
{
    const int row = blockIdx.x;
    const int tid = threadIdx.x;
    const size_t off = (size_t)row * Cq + tid * 4;

    float4 v = *(const float4*)&in[off];
    float s = v.x + v.y + v.z + v.w;
    float ss = v.x * v.x + v.y * v.y + v.z * v.z + v.w * v.w;

#pragma unroll
    for (int o2 = 16; o2 > 0; o2 >>= 1) {
        s  += __shfl_xor_sync(0xffffffffu, s,  o2);
        ss += __shfl_xor_sync(0xffffffffu, ss, o2);
    }
    __shared__ float sh_s[8], sh_ss[8], red[2];
    if ((tid & 31) == 0) { sh_s[tid >> 5] = s; sh_ss[tid >> 5] = ss; }
    __syncthreads();
    if (tid < 32) {
        float a  = (tid < 8) ? sh_s[tid]  : 0.f;
        float a2 = (tid < 8) ? sh_ss[tid] : 0.f;
#pragma unroll
        for (int o2 = 4; o2 > 0; o2 >>= 1) {
            a  += __shfl_xor_sync(0xffffffffu, a,  o2);
            a2 += __shfl_xor_sync(0xffffffffu, a2, o2);
        }
        if (tid == 0) {
            float mean = a * (1.f / Cq);
            float var = a2 * (1.f / Cq) - mean * mean;
            red[0] = mean;
            red[1] = rsqrtf(var + EPSLN);
        }
    }
    __syncthreads();
    float mean = red[0], inv = red[1];

    float4 gv = *(const float4*)&g[tid * 4];
    float4 bv = *(const float4*)&bt[tid * 4];
    float4 rv = *(const float4*)&res[off];
    float4 o;
    o.x = rv.x + (v.x - mean) * inv * gv.x + bv.x;
    o.y = rv.y + (v.y - mean) * inv * gv.y + bv.y;
    o.z = rv.z + (v.z - mean) * inv * gv.z + bv.z;
    o.w = rv.w + (v.w - mean) * inv * gv.w + bv.w;
    *(float4*)&out[off] = o;
}

// ---------------------------------------------------------------------------
// host launcher
// ---------------------------------------------------------------------------
extern "C" void kernel_launch(void* const* d_in, const int* in_sizes, int n_in,
                              void* d_out, int out_size)
{
    const float* x      = (const float*)d_in[0];
    const float* qkv_w  = (const float*)d_in[1];
    const float* qkv_b  = (const float*)d_in[2];
    const float* proj_w = (const float*)d_in[3];
    const float* proj_b = (const float*)d_in[4];
    const float* n1_g   = (const float*)d_in[5];
    const float* n1_b   = (const float*)d_in[6];
    const float* fc1_w  = (const float*)d_in[7];
    const float* fc1_b  = (const float*)d_in[8];
    const float* fc2_w  = (const float*)d_in[9];
    const float* fc2_b  = (const float*)d_in[10];
    const float* n2_g   = (const float*)d_in[11];
    const float* n2_b   = (const float*)d_in[12];
    float* out = (float*)d_out;

    static float *p_qkv = nullptr, *p_att, *p_a, *p_y1, *p_h1, *p_h2;
    if (!p_qkv) {
        cudaGetSymbolAddress((void**)&p_qkv, g_qkv);
        cudaGetSymbolAddress((void**)&p_att, g_att);
        cudaGetSymbolAddress((void**)&p_a,   g_a);
        cudaGetSymbolAddress((void**)&p_y1,  g_y1);
        cudaGetSymbolAddress((void**)&p_h1,  g_h1);
        cudaGetSymbolAddress((void**)&p_h2,  g_h2);
        cudaFuncSetAttribute(attn_kernel, cudaFuncAttributeMaxDynamicSharedMemorySize,
                             ATT_SMEM_FLOATS * sizeof(float));
    }

    // 1) qkv = x @ qkv_w + qkv_b          [8192,1024] x [1024,3072]
    gemm_tf32_kernel<<<dim3(3 * Cq / 128, Mrows / 128), 256>>>(
        x, qkv_w, qkv_b, p_qkv, Mrows, 3 * Cq, Cq, 0);

    // 2) attention -> p_att [8192,1024]
    attn_kernel<<<dim3(Nq / 64, Bq * Hq), 256, ATT_SMEM_FLOATS * sizeof(float)>>>(
        p_qkv, p_att);

    // 3) a = att @ proj_w + proj_b
    gemm_tf32_kernel<<<dim3(Cq / 128, Mrows / 128), 256>>>(
        p_att, proj_w, proj_b, p_a, Mrows, Cq, Cq, 0);

    // 4) y1 = a + LN(a)
    ln_add_kernel<<<Mrows, 256>>>(p_a, p_a, n1_g, n1_b, p_y1);

    // 5) h1 = GELU(y1 @ fc1_w + fc1_b)    [8192,1024] x [1024,4096]
    gemm_tf32_kernel<<<dim3(4 * Cq / 128, Mrows / 128), 256>>>(
        p_y1, fc1_w, fc1_b, p_h1, Mrows, 4 * Cq, Cq, 1);

    // 6) h2 = h1 @ fc2_w + fc2_b          [8192,4096] x [4096,1024]
    gemm_tf32_kernel<<<dim3(Cq / 128, Mrows / 128), 256>>>(
        p_h1, fc2_w, fc2_b, p_h2, Mrows, Cq, 4 * Cq, 0);

    // 7) out = y1 + LN(h2)
    ln_add_kernel<<<Mrows, 256>>>(p_h2, p_y1, n2_g, n2_b, out);
}

// round 5
// speedup vs baseline: 3.0516x; 1.4697x over previous
#include <cuda_runtime.h>
#include <cuda_bf16.h>
#include <math.h>
#include <stdint.h>

// ---------------------------------------------------------------------------
// ViT block, all matmul on mma.sync tf32 (sm_100 non-'a' target: no tcgen05).
//   qkv = x @ qkv_w + qkv_b            (gemm_tc32, output tf32-rounded)
//   flash-attention per (b,h)          (attn_mma, tf32 fragments)
//   a  = att @ proj_w + proj_b         (gemm_tc32)
//   y1 = a + LN(a; n1)                 (ln_add, rounded)
//   h1 = GELU(y1 @ fc1_w + fc1_b)      (gemm_tc32, rounded)
//   h2 = h1 @ fc2_w + fc2_b            (gemm_tc32)
//   out = y1 + LN(h2; n2)              (ln_add)
// All mma operands pre-rounded to tf32-rna in memory.
// ---------------------------------------------------------------------------

#define Bq   8
#define Nq   1024
#define Cq   1024
#define Mrows (Bq*Nq)          // 8192
#define SCALE 0.125f
#define EPSLN 1e-6f

#define FLAG_GELU  1
#define FLAG_ROUND 2

// Scratch (static device memory)
__device__ float g_qkv[Mrows * 3 * Cq];
__device__ float g_att[Mrows * Cq];
__device__ float g_a  [Mrows * Cq];
__device__ float g_y1 [Mrows * Cq];
__device__ float g_h1 [Mrows * 4 * Cq];
__device__ float g_h2 [Mrows * Cq];
__device__ float g_xr [Mrows * Cq];
__device__ float g_wqkv_r[Cq * 3 * Cq];
__device__ float g_wproj_r[Cq * Cq];
__device__ float g_wfc1_r[Cq * 4 * Cq];
__device__ float g_wfc2_r[4 * Cq * Cq];

__device__ __forceinline__ uint32_t f2tf32(float f) {
    uint32_t u;
    asm("cvt.rna.tf32.f32 %0, %1;" : "=r"(u) : "f"(f));
    return u;
}
__device__ __forceinline__ float rna32(float f) { return __uint_as_float(f2tf32(f)); }

__device__ __forceinline__ uint32_t smem_u32(const void* p) {
    uint32_t a;
    asm("{ .reg .u64 t; cvta.to.shared.u64 t, %1; cvt.u32.u64 %0, t; }" : "=r"(a) : "l"(p));
    return a;
}

#define MMA_TF32(d, a, b)                                                  \
    asm volatile(                                                          \
        "mma.sync.aligned.m16n8k8.row.col.f32.tf32.tf32.f32 "              \
        "{%0,%1,%2,%3}, {%4,%5,%6,%7}, {%8,%9}, {%0,%1,%2,%3};"            \
        : "+f"(d[0]), "+f"(d[1]), "+f"(d[2]), "+f"(d[3])                   \
        : "r"(a[0]), "r"(a[1]), "r"(a[2]), "r"(a[3]), "r"(b[0]), "r"(b[1]))

#define CP_ASYNC16(dst, src) \
    asm volatile("cp.async.cg.shared.global [%0], [%1], 16;" :: "r"(dst), "l"(src))
#define CP_COMMIT() asm volatile("cp.async.commit_group;" ::: "memory")
#define CP_WAIT(n)  asm volatile("cp.async.wait_group %0;" :: "n"(n) : "memory")

extern __shared__ __align__(16) char g_dynsmem[];

// ---------------------------------------------------------------------------
// tf32 mma GEMM: C[M,N] = A[M,K] @ B[K,N] + bias (+GELU, +tf32 round)
// 128x128 tile, BK=16, 4-stage cp.async, 256 threads (8 warps of 64x32).
// A and B pre-rounded to tf32-rna. Dyn smem 75776 B.
// stage layout: As [128][20] floats then Bs [16][136] floats (4736 floats).
// ---------------------------------------------------------------------------
__global__ __launch_bounds__(256, 2) void gemm_tc32(
    const float* __restrict__ A, const float* __restrict__ B,
    const float* __restrict__ bias, float* __restrict__ C,
    int N, int K, int flags)
{
    float* sm = (float*)g_dynsmem;
    const uint32_t smu = smem_u32(sm);

    const int tid  = threadIdx.x;
    const int lane = tid & 31;
    const int warp = tid >> 5;
    const int gid  = lane >> 2;
    const int tig  = lane & 3;
    const int wm   = (warp >> 2) * 64;
    const int wn   = (warp & 3) * 32;
    const int bm   = blockIdx.y * 128;
    const int bn   = blockIdx.x * 128;

    const int c1 = tid + 256;
    const int ar0 = tid >> 2, ac0 = (tid & 3) << 2;
    const int ar1 = c1 >> 2,  ac1 = (c1 & 3) << 2;
    const int br0 = tid >> 5, bc0 = (tid & 31) << 2;
    const int br1 = c1 >> 5,  bc1 = (c1 & 31) << 2;

    float acc[4][4][4];
#pragma unroll
    for (int mt = 0; mt < 4; mt++)
#pragma unroll
        for (int nt = 0; nt < 4; nt++)
#pragma unroll
            for (int r = 0; r < 4; r++) acc[mt][nt][r] = 0.f;

    const int T = K >> 4;

#define GEMM_ISSUE(t)                                                           \
    do {                                                                        \
        const int s_ = (t) & 3;                                                 \
        const uint32_t as_ = smu + (uint32_t)(s_ * 4736 * 4);                   \
        const uint32_t bs_ = as_ + 2560 * 4;                                    \
        CP_ASYNC16(as_ + (ar0 * 20 + ac0) * 4, &A[(size_t)(bm + ar0) * K + (t) * 16 + ac0]); \
        CP_ASYNC16(as_ + (ar1 * 20 + ac1) * 4, &A[(size_t)(bm + ar1) * K + (t) * 16 + ac1]); \
        CP_ASYNC16(bs_ + (br0 * 136 + bc0) * 4, &B[(size_t)((t) * 16 + br0) * N + bn + bc0]); \
        CP_ASYNC16(bs_ + (br1 * 136 + bc1) * 4, &B[(size_t)((t) * 16 + br1) * N + bn + bc1]); \
        CP_COMMIT();                                                            \
    } while (0)

    GEMM_ISSUE(0); GEMM_ISSUE(1); GEMM_ISSUE(2);

    for (int t = 0; t < T; t++) {
        if (t < T - 2)      { CP_WAIT(2); }
        else if (t == T - 2){ CP_WAIT(1); }
        else                { CP_WAIT(0); }
        __syncthreads();
        if (t + 3 < T) GEMM_ISSUE(t + 3);

        const uint32_t* As = (const uint32_t*)(sm + (t & 3) * 4736);
        const uint32_t* Bs = As + 2560;
#pragma unroll
        for (int ks = 0; ks < 2; ks++) {
            const int k0 = ks * 8;
            uint32_t afr[4][4], bfr[4][2];
#pragma unroll
            for (int mt = 0; mt < 4; mt++) {
                const int m = wm + mt * 16 + gid;
                afr[mt][0] = As[m * 20 + k0 + tig];
                afr[mt][1] = As[(m + 8) * 20 + k0 + tig];
                afr[mt][2] = As[m * 20 + k0 + tig + 4];
                afr[mt][3] = As[(m + 8) * 20 + k0 + tig + 4];
            }
#pragma unroll
            for (int nt = 0; nt < 4; nt++) {
                const int n = wn + nt * 8 + gid;
                bfr[nt][0] = Bs[(k0 + tig) * 136 + n];
                bfr[nt][1] = Bs[(k0 + tig + 4) * 136 + n];
            }
#pragma unroll
            for (int mt = 0; mt < 4; mt++)
#pragma unroll
                for (int nt = 0; nt < 4; nt++)
                    MMA_TF32(acc[mt][nt], afr[mt], bfr[nt]);
        }
    }
#undef GEMM_ISSUE

    const int gelu = flags & FLAG_GELU;
    const int rnd  = flags & FLAG_ROUND;
#pragma unroll
    for (int mt = 0; mt < 4; mt++) {
        const int row0 = bm + wm + mt * 16 + gid;
#pragma unroll
        for (int nt = 0; nt < 4; nt++) {
            const int col = bn + wn + nt * 8 + tig * 2;
            float2 bv = *(const float2*)&bias[col];
            float c0 = acc[mt][nt][0] + bv.x;
            float c1 = acc[mt][nt][1] + bv.y;
            float c2 = acc[mt][nt][2] + bv.x;
            float c3 = acc[mt][nt][3] + bv.y;
            if (gelu) {
                c0 = 0.5f * c0 * (1.f + erff(c0 * 0.70710678118654752f));
                c1 = 0.5f * c1 * (1.f + erff(c1 * 0.70710678118654752f));
                c2 = 0.5f * c2 * (1.f + erff(c2 * 0.70710678118654752f));
                c3 = 0.5f * c3 * (1.f + erff(c3 * 0.70710678118654752f));
            }
            if (rnd) {
                c0 = rna32(c0); c1 = rna32(c1); c2 = rna32(c2); c3 = rna32(c3);
            }
            float2 o01; o01.x = c0; o01.y = c1;
            float2 o23; o23.x = c2; o23.y = c3;
            *(float2*)&C[(size_t)row0 * N + col] = o01;
            *(float2*)&C[(size_t)(row0 + 8) * N + col] = o23;
        }
    }
}

// ---------------------------------------------------------------------------
// Flash attention on mma.sync tf32. grid (Nq/64, B*H), 128 threads (4 warps).
// Each warp owns 16 q-rows. Q fragments register-resident. P per-warp in smem.
// Smem floats: Qs/Ps [64][68] | Ks [64][68] | Vs [64][72]  (53248 B)
// ---------------------------------------------------------------------------
#define AQ_STR 68
#define AK_STR 68
#define AV_STR 72
#define ATTN_SMEM ((64*AQ_STR + 64*AK_STR + 64*AV_STR) * 4)

__global__ __launch_bounds__(128, 2) void attn_mma(
    const float* __restrict__ qkv, float* __restrict__ out)
{
    float* sm = (float*)g_dynsmem;
    float* Qs = sm;                       // also Ps after Q frags extracted
    float* Ks = sm + 64 * AQ_STR;
    float* Vs = Ks + 64 * AK_STR;

    const int bh = blockIdx.y;
    const int b = bh >> 4;
    const int h = bh & 15;
    const int q0 = blockIdx.x * 64;
    const int tid = threadIdx.x;
    const int wid = tid >> 5;
    const int lane = tid & 31;
    const int gid = lane >> 2;
    const int tig = lane & 3;
    const int row0 = wid * 16 + gid;      // warp-local q row (and +8)

    const size_t base = (size_t)b * Nq * (3 * Cq);

    // load Q tile (scaled; SCALE is a power of 2, preserves tf32)
#pragma unroll
    for (int i = 0; i < 8; i++) {
        int idx = tid + i * 128;
        int r = idx >> 4;
        int c = (idx & 15) << 2;
        float4 v = *(const float4*)&qkv[base + (size_t)(q0 + r) * (3 * Cq) + h * 64 + c];
        Qs[r * AQ_STR + c + 0] = v.x * SCALE;
        Qs[r * AQ_STR + c + 1] = v.y * SCALE;
        Qs[r * AQ_STR + c + 2] = v.z * SCALE;
        Qs[r * AQ_STR + c + 3] = v.w * SCALE;
    }
    __syncthreads();

    // extract Q a-fragments (8 k-steps of 8)
    uint32_t qf[8][4];
#pragma unroll
    for (int ks = 0; ks < 8; ks++) {
        qf[ks][0] = __float_as_uint(Qs[row0 * AQ_STR + ks * 8 + tig]);
        qf[ks][1] = __float_as_uint(Qs[(row0 + 8) * AQ_STR + ks * 8 + tig]);
        qf[ks][2] = __float_as_uint(Qs[row0 * AQ_STR + ks * 8 + tig + 4]);
        qf[ks][3] = __float_as_uint(Qs[(row0 + 8) * AQ_STR + ks * 8 + tig + 4]);
    }

    float of[8][4];
#pragma unroll
    for (int nt = 0; nt < 8; nt++)
#pragma unroll
        for (int r = 0; r < 4; r++) of[nt][r] = 0.f;
    float m0 = -INFINITY, m1 = -INFINITY, l0 = 0.f, l1 = 0.f;

    for (int kt = 0; kt < Nq; kt += 64) {
        __syncthreads();   // all warps done with previous K/V (and P reads)
        // load K and V tiles
#pragma unroll
        for (int i = 0; i < 8; i++) {
            int idx = tid + i * 128;
            int r = idx >> 4;
            int c = (idx & 15) << 2;
            float4 kv = *(const float4*)&qkv[base + (size_t)(kt + r) * (3 * Cq) + Cq + h * 64 + c];
            *(float4*)&Ks[r * AK_STR + c] = kv;
            float4 vv = *(const float4*)&qkv[base + (size_t)(kt + r) * (3 * Cq) + 2 * Cq + h * 64 + c];
            *(float4*)&Vs[r * AV_STR + c] = vv;
        }
        __syncthreads();

        // S = Q @ K^T : per-warp 16x64, 8 n-tiles x 8 k-steps
        float sf[8][4];
#pragma unroll
        for (int nt = 0; nt < 8; nt++)
#pragma unroll
            for (int r = 0; r < 4; r++) sf[nt][r] = 0.f;
#pragma unroll
        for (int ks = 0; ks < 8; ks++) {
#pragma unroll
            for (int nt = 0; nt < 8; nt++) {
                uint32_t bfr[2];
                bfr[0] = __float_as_uint(Ks[(nt * 8 + gid) * AK_STR + ks * 8 + tig]);
                bfr[1] = __float_as_uint(Ks[(nt * 8 + gid) * AK_STR + ks * 8 + tig + 4]);
                MMA_TF32(sf[nt], qf[ks], bfr);
            }
        }

        // online softmax: row gid (c0,c1) and row gid+8 (c2,c3)
        float mx0 = -INFINITY, mx1 = -INFINITY;
#pragma unroll
        for (int nt = 0; nt < 8; nt++) {
            mx0 = fmaxf(mx0, fmaxf(sf[nt][0], sf[nt][1]));
            mx1 = fmaxf(mx1, fmaxf(sf[nt][2], sf[nt][3]));
        }
        mx0 = fmaxf(mx0, __shfl_xor_sync(0xffffffffu, mx0, 1));
        mx0 = fmaxf(mx0, __shfl_xor_sync(0xffffffffu, mx0, 2));
        mx1 = fmaxf(mx1, __shfl_xor_sync(0xffffffffu, mx1, 1));
        mx1 = fmaxf(mx1, __shfl_xor_sync(0xffffffffu, mx1, 2));
        const float mn0 = fmaxf(m0, mx0);
        const float mn1 = fmaxf(m1, mx1);
        const float cr0 = __expf(m0 - mn0);
        const float cr1 = __expf(m1 - mn1);
        float rs0 = 0.f, rs1 = 0.f;
#pragma unroll
        for (int nt = 0; nt < 8; nt++) {
            float p0 = __expf(sf[nt][0] - mn0);
            float p1 = __expf(sf[nt][1] - mn0);
            float p2 = __expf(sf[nt][2] - mn1);
            float p3 = __expf(sf[nt][3] - mn1);
            rs0 += p0 + p1;
            rs1 += p2 + p3;
            Qs[row0 * AQ_STR + nt * 8 + tig * 2]           = rna32(p0);
            Qs[row0 * AQ_STR + nt * 8 + tig * 2 + 1]       = rna32(p1);
            Qs[(row0 + 8) * AQ_STR + nt * 8 + tig * 2]     = rna32(p2);
            Qs[(row0 + 8) * AQ_STR + nt * 8 + tig * 2 + 1] = rna32(p3);
            of[nt][0] *= cr0; of[nt][1] *= cr0;
            of[nt][2] *= cr1; of[nt][3] *= cr1;
        }
        rs0 += __shfl_xor_sync(0xffffffffu, rs0, 1);
        rs0 += __shfl_xor_sync(0xffffffffu, rs0, 2);
        rs1 += __shfl_xor_sync(0xffffffffu, rs1, 1);
        rs1 += __shfl_xor_sync(0xffffffffu, rs1, 2);
        m0 = mn0; m1 = mn1;
        l0 = l0 * cr0 + rs0;
        l1 = l1 * cr1 + rs1;
        __syncwarp();   // P rows are warp-private

        // O += P @ V : 8 key-steps x 8 d-tiles
#pragma unroll
        for (int ks = 0; ks < 8; ks++) {
            uint32_t pf[4];
            pf[0] = __float_as_uint(Qs[row0 * AQ_STR + ks * 8 + tig]);
            pf[1] = __float_as_uint(Qs[(row0 + 8) * AQ_STR + ks * 8 + tig]);
            pf[2] = __float_as_uint(Qs[row0 * AQ_STR + ks * 8 + tig + 4]);
            pf[3] = __float_as_uint(Qs[(row0 + 8) * AQ_STR + ks * 8 + tig + 4]);
#pragma unroll
            for (int nt = 0; nt < 8; nt++) {
                uint32_t bfr[2];
                bfr[0] = __float_as_uint(Vs[(ks * 8 + tig) * AV_STR + nt * 8 + gid]);
                bfr[1] = __float_as_uint(Vs[(ks * 8 + tig + 4) * AV_STR + nt * 8 + gid]);
                MMA_TF32(of[nt], pf, bfr);
            }
        }
        __syncwarp();
    }

    // epilogue: normalize, round (feeds proj gemm), store
    const float inv0 = 1.f / l0;
    const float inv1 = 1.f / l1;
    const size_t grow0 = (size_t)b * Nq + q0 + row0;
#pragma unroll
    for (int nt = 0; nt < 8; nt++) {
        const int col = h * 64 + nt * 8 + tig * 2;
        float2 a; a.x = rna32(of[nt][0] * inv0); a.y = rna32(of[nt][1] * inv0);
        float2 c; c.x = rna32(of[nt][2] * inv1); c.y = rna32(of[nt][3] * inv1);
        *(float2*)&out[grow0 * Cq + col] = a;
        *(float2*)&out[(grow0 + 8) * Cq + col] = c;
    }
}

// ---------------------------------------------------------------------------
// elementwise tf32-rna rounding copy
// ---------------------------------------------------------------------------
__global__ __launch_bounds__(256) void round_copy(
    const float* __restrict__ in, float* __restrict__ out)
{
    const size_t i = ((size_t)blockIdx.x * 256 + threadIdx.x) * 4;
    float4 v = *(const float4*)&in[i];
    v.x = rna32(v.x); v.y = rna32(v.y); v.z = rna32(v.z); v.w = rna32(v.w);
    *(float4*)&out[i] = v;
}

// ---------------------------------------------------------------------------
// out[row] = res[row] + LayerNorm(in[row]) * g + b   (optionally tf32-rounded)
// ---------------------------------------------------------------------------
__global__ __launch_bounds__(256) void ln_add_kernel(
    const float* __restrict__ in, const float* __restrict__ res,
    const float* __restrict__ g, const float* __restrict__ bt,
    float* __restrict__ out, int rnd)
{
    const int row = blockIdx.x;
    const int tid = threadIdx.x;
    const size_t off = (size_t)row * Cq + tid * 4;

    float4 v = *(const float4*)&in[off];
    float s = v.x + v.y + v.z + v.w;
    float ss = v.x * v.x + v.y * v.y + v.z * v.z + v.w * v.w;

#pragma unroll
    for (int o2 = 16; o2 > 0; o2 >>= 1) {
        s  += __shfl_xor_sync(0xffffffffu, s,  o2);
        ss += __shfl_xor_sync(0xffffffffu, ss, o2);
    }
    __shared__ float sh_s[8], sh_ss[8], red[2];
    if ((tid & 31) == 0) { sh_s[tid >> 5] = s; sh_ss[tid >> 5] = ss; }
    __syncthreads();
    if (tid < 32) {
        float a  = (tid < 8) ? sh_s[tid]  : 0.f;
        float a2 = (tid < 8) ? sh_ss[tid] : 0.f;
#pragma unroll
        for (int o2 = 4; o2 > 0; o2 >>= 1) {
            a  += __shfl_xor_sync(0xffffffffu, a,  o2);
            a2 += __shfl_xor_sync(0xffffffffu, a2, o2);
        }
        if (tid == 0) {
            float mean = a * (1.f / Cq);
            float var = a2 * (1.f / Cq) - mean * mean;
            red[0] = mean;
            red[1] = rsqrtf(var + EPSLN);
        }
    }
    __syncthreads();
    float mean = red[0], inv = red[1];

    float4 gv = *(const float4*)&g[tid * 4];
    float4 bv = *(const float4*)&bt[tid * 4];
    float4 rv = *(const float4*)&res[off];
    float4 o;
    o.x = rv.x + (v.x - mean) * inv * gv.x + bv.x;
    o.y = rv.y + (v.y - mean) * inv * gv.y + bv.y;
    o.z = rv.z + (v.z - mean) * inv * gv.z + bv.z;
    o.w = rv.w + (v.w - mean) * inv * gv.w + bv.w;
    if (rnd) { o.x = rna32(o.x); o.y = rna32(o.y); o.z = rna32(o.z); o.w = rna32(o.w); }
    *(float4*)&out[off] = o;
}

// ---------------------------------------------------------------------------
// host launcher
// ---------------------------------------------------------------------------
#define GEMM_SMEM 75776

extern "C" void kernel_launch(void* const* d_in, const int* in_sizes, int n_in,
                              void* d_out, int out_size)
{
    const float* x      = (const float*)d_in[0];
    const float* qkv_w  = (const float*)d_in[1];
    const float* qkv_b  = (const float*)d_in[2];
    const float* proj_w = (const float*)d_in[3];
    const float* proj_b = (const float*)d_in[4];
    const float* n1_g   = (const float*)d_in[5];
    const float* n1_b   = (const float*)d_in[6];
    const float* fc1_w  = (const float*)d_in[7];
    const float* fc1_b  = (const float*)d_in[8];
    const float* fc2_w  = (const float*)d_in[9];
    const float* fc2_b  = (const float*)d_in[10];
    const float* n2_g   = (const float*)d_in[11];
    const float* n2_b   = (const float*)d_in[12];
    float* out = (float*)d_out;

    static float *p_qkv = nullptr, *p_att, *p_a, *p_y1, *p_h1, *p_h2, *p_xr,
                 *p_wqkv, *p_wproj, *p_wfc1, *p_wfc2;
    if (!p_qkv) {
        cudaGetSymbolAddress((void**)&p_qkv, g_qkv);
        cudaGetSymbolAddress((void**)&p_att, g_att);
        cudaGetSymbolAddress((void**)&p_a,   g_a);
        cudaGetSymbolAddress((void**)&p_y1,  g_y1);
        cudaGetSymbolAddress((void**)&p_h1,  g_h1);
        cudaGetSymbolAddress((void**)&p_h2,  g_h2);
        cudaGetSymbolAddress((void**)&p_xr,  g_xr);
        cudaGetSymbolAddress((void**)&p_wqkv, g_wqkv_r);
        cudaGetSymbolAddress((void**)&p_wproj, g_wproj_r);
        cudaGetSymbolAddress((void**)&p_wfc1, g_wfc1_r);
        cudaGetSymbolAddress((void**)&p_wfc2, g_wfc2_r);
        cudaFuncSetAttribute(gemm_tc32, cudaFuncAttributeMaxDynamicSharedMemorySize, GEMM_SMEM);
        cudaFuncSetAttribute(attn_mma, cudaFuncAttributeMaxDynamicSharedMemorySize, ATTN_SMEM);
    }

    // 0) pre-round x and weights to tf32-rna (raw [K,N] layout, no transpose)
    round_copy<<<Mrows * Cq / 1024, 256>>>(x, p_xr);
    round_copy<<<Cq * 3 * Cq / 1024, 256>>>(qkv_w, p_wqkv);
    round_copy<<<Cq * Cq / 1024, 256>>>(proj_w, p_wproj);
    round_copy<<<Cq * 4 * Cq / 1024, 256>>>(fc1_w, p_wfc1);
    round_copy<<<4 * Cq * Cq / 1024, 256>>>(fc2_w, p_wfc2);

    // 1) qkv = x @ qkv_w + qkv_b   (rounded: feeds attention mma)
    gemm_tc32<<<dim3(3 * Cq / 128, Mrows / 128), 256, GEMM_SMEM>>>(
        p_xr, p_wqkv, qkv_b, p_qkv, 3 * Cq, Cq, FLAG_ROUND);

    // 2) attention (tf32 mma flash) -> p_att (rounded)
    attn_mma<<<dim3(Nq / 64, Bq * 16), 128, ATTN_SMEM>>>(p_qkv, p_att);

    // 3) a = att @ proj_w + proj_b
    gemm_tc32<<<dim3(Cq / 128, Mrows / 128), 256, GEMM_SMEM>>>(
        p_att, p_wproj, proj_b, p_a, Cq, Cq, 0);

    // 4) y1 = a + LN(a)   (rounded: feeds fc1)
    ln_add_kernel<<<Mrows, 256>>>(p_a, p_a, n1_g, n1_b, p_y1, 1);

    // 5) h1 = GELU(y1 @ fc1_w + fc1_b)   (rounded: feeds fc2)
    gemm_tc32<<<dim3(4 * Cq / 128, Mrows / 128), 256, GEMM_SMEM>>>(
        p_y1, p_wfc1, fc1_b, p_h1, 4 * Cq, Cq, FLAG_GELU | FLAG_ROUND);

    // 6) h2 = h1 @ fc2_w + fc2_b
    gemm_tc32<<<dim3(Cq / 128, Mrows / 128), 256, GEMM_SMEM>>>(
        p_h1, p_wfc2, fc2_b, p_h2, Cq, 4 * Cq, 0);

    // 7) out = y1 + LN(h2)
    ln_add_kernel<<<Mrows, 256>>>(p_h2, p_y1, n2_g, n2_b, out, 0);
}

// round 6
// speedup vs baseline: 5.2484x; 1.7199x over previous
#include <cuda_runtime.h>
#include <cuda_fp16.h>
#include <math.h>
#include <stdint.h>

// ---------------------------------------------------------------------------
// ViT block, all matmul on mma.sync fp16 (fp32 accumulate). fp16 mantissa ==
// tf32 mantissa (10 bits), so error matches the round-5 tf32 kernel while
// mma.m16n8k16 doubles FLOP/issue vs m16n8k8.
//   qkv = x @ qkv_w + qkv_b            (gemm_fp16 -> half)
//   flash-attention per (b,h)          (attn_fp16, fp16 mma, fp32 softmax)
//   a  = att @ proj_w + proj_b         (gemm_fp16 -> fp32)
//   y1 = a + LN(a; n1)                 (ln_add -> fp32 + half)
//   h1 = GELU(y1 @ fc1_w + fc1_b)      (gemm_fp16 -> half)
//   h2 = h1 @ fc2_w + fc2_b            (gemm_fp16 -> fp32)
//   out = y1 + LN(h2; n2)              (ln_add -> fp32)
// ---------------------------------------------------------------------------

#define Bq   8
#define Nq   1024
#define Cq   1024
#define Mrows (Bq*Nq)          // 8192
#define EPSLN 1e-6f

// Scratch (static device memory)
__device__ __half g_xh  [Mrows * Cq];
__device__ __half g_qkvh[Mrows * 3 * Cq];
__device__ __half g_atth[Mrows * Cq];
__device__ float  g_a   [Mrows * Cq];
__device__ float  g_y1  [Mrows * Cq];
__device__ __half g_y1h [Mrows * Cq];
__device__ __half g_h1h [Mrows * 4 * Cq];
__device__ float  g_h2  [Mrows * Cq];
__device__ __half g_wqkvT[3 * Cq * Cq];    // [3072][1024]
__device__ __half g_wprojT[Cq * Cq];       // [1024][1024]
__device__ __half g_wfc1T[4 * Cq * Cq];    // [4096][1024]
__device__ __half g_wfc2T[Cq * 4 * Cq];    // [1024][4096]

__device__ __forceinline__ uint32_t smem_u32(const void* p) {
    uint32_t a;
    asm("{ .reg .u64 t; cvta.to.shared.u64 t, %1; cvt.u32.u64 %0, t; }" : "=r"(a) : "l"(p));
    return a;
}

#define MMA_F16(d, a, b)                                                   \
    asm volatile(                                                          \
        "mma.sync.aligned.m16n8k16.row.col.f32.f16.f16.f32 "               \
        "{%0,%1,%2,%3}, {%4,%5,%6,%7}, {%8,%9}, {%0,%1,%2,%3};"            \
        : "+f"(d[0]), "+f"(d[1]), "+f"(d[2]), "+f"(d[3])                   \
        : "r"(a[0]), "r"(a[1]), "r"(a[2]), "r"(a[3]), "r"(b[0]), "r"(b[1]))

#define CP_ASYNC16(dst, src) \
    asm volatile("cp.async.cg.shared.global [%0], [%1], 16;" :: "r"(dst), "l"(src))
#define CP_COMMIT() asm volatile("cp.async.commit_group;" ::: "memory")
#define CP_WAIT(n)  asm volatile("cp.async.wait_group %0;" :: "n"(n) : "memory")

extern __shared__ __align__(16) char g_dynsmem[];

// ---------------------------------------------------------------------------
// fp16 mma GEMM: C[M,N] = A[M,K] @ Bt[N,K]^T + bias (+GELU).
// A half [M,K], Bt half [N,K] (weights pre-transposed). 128x128 tile, BK=32,
// 4-stage cp.async, 256 threads (8 warps, 64x32 warp tiles).
// Stage: A 128 rows x 40 halves (stride 20 u32) + B same = 20480 B.
// Outputs to fp32 C and/or half Ch (whichever non-null).
// ---------------------------------------------------------------------------
#define GEMM_SMEM 81920

__global__ __launch_bounds__(256, 2) void gemm_fp16(
    const __half* __restrict__ A, const __half* __restrict__ Bt,
    const float* __restrict__ bias, float* __restrict__ Cf,
    __half* __restrict__ Ch, int N, int K, int gelu)
{
    const uint32_t smu = smem_u32(g_dynsmem);

    const int tid  = threadIdx.x;
    const int lane = tid & 31;
    const int warp = tid >> 5;
    const int gid  = lane >> 2;
    const int tig  = lane & 3;
    const int wm   = (warp >> 2) * 64;
    const int wn   = (warp & 3) * 32;
    const int bm   = blockIdx.y * 128;
    const int bn   = blockIdx.x * 128;

    const int c1 = tid + 256;
    const int r0 = tid >> 2, q0c = (tid & 3);
    const int r1 = c1 >> 2,  q1c = (c1 & 3);

    float acc[4][4][4];
#pragma unroll
    for (int mt = 0; mt < 4; mt++)
#pragma unroll
        for (int nt = 0; nt < 4; nt++)
#pragma unroll
            for (int r = 0; r < 4; r++) acc[mt][nt][r] = 0.f;

    const int T = K >> 5;

#define GEMM_ISSUE(t)                                                            \
    do {                                                                         \
        const uint32_t sb_ = smu + (uint32_t)(((t) & 3) * 20480);                \
        CP_ASYNC16(sb_ + r0 * 80 + q0c * 16, &A[(size_t)(bm + r0) * K + (t) * 32 + q0c * 8]); \
        CP_ASYNC16(sb_ + r1 * 80 + q1c * 16, &A[(size_t)(bm + r1) * K + (t) * 32 + q1c * 8]); \
        CP_ASYNC16(sb_ + 10240 + r0 * 80 + q0c * 16, &Bt[(size_t)(bn + r0) * K + (t) * 32 + q0c * 8]); \
        CP_ASYNC16(sb_ + 10240 + r1 * 80 + q1c * 16, &Bt[(size_t)(bn + r1) * K + (t) * 32 + q1c * 8]); \
        CP_COMMIT();                                                             \
    } while (0)

    GEMM_ISSUE(0); GEMM_ISSUE(1); GEMM_ISSUE(2);

    for (int t = 0; t < T; t++) {
        if (t < T - 2)      { CP_WAIT(2); }
        else if (t == T - 2){ CP_WAIT(1); }
        else                { CP_WAIT(0); }
        __syncthreads();
        if (t + 3 < T) GEMM_ISSUE(t + 3);

        const uint32_t* As = (const uint32_t*)(g_dynsmem + (t & 3) * 20480);
        const uint32_t* Bs = As + 2560;
#pragma unroll
        for (int ks = 0; ks < 2; ks++) {
            const int k0u = ks * 8;
            uint32_t afr[4][4], bfr[4][2];
#pragma unroll
            for (int mt = 0; mt < 4; mt++) {
                const int m = wm + mt * 16 + gid;
                afr[mt][0] = As[m * 20 + k0u + tig];
                afr[mt][1] = As[(m + 8) * 20 + k0u + tig];
                afr[mt][2] = As[m * 20 + k0u + tig + 4];
                afr[mt][3] = As[(m + 8) * 20 + k0u + tig + 4];
            }
#pragma unroll
            for (int nt = 0; nt < 4; nt++) {
                const int n = wn + nt * 8 + gid;
                bfr[nt][0] = Bs[n * 20 + k0u + tig];
                bfr[nt][1] = Bs[n * 20 + k0u + tig + 4];
            }
#pragma unroll
            for (int mt = 0; mt < 4; mt++)
#pragma unroll
                for (int nt = 0; nt < 4; nt++)
                    MMA_F16(acc[mt][nt], afr[mt], bfr[nt]);
        }
    }
#undef GEMM_ISSUE

#pragma unroll
    for (int mt = 0; mt < 4; mt++) {
        const int row0 = bm + wm + mt * 16 + gid;
#pragma unroll
        for (int nt = 0; nt < 4; nt++) {
            const int col = bn + wn + nt * 8 + tig * 2;
            float2 bv = *(const float2*)&bias[col];
            float c0 = acc[mt][nt][0] + bv.x;
            float c1 = acc[mt][nt][1] + bv.y;
            float c2 = acc[mt][nt][2] + bv.x;
            float c3 = acc[mt][nt][3] + bv.y;
            if (gelu) {
                c0 = 0.5f * c0 * (1.f + erff(c0 * 0.70710678118654752f));
                c1 = 0.5f * c1 * (1.f + erff(c1 * 0.70710678118654752f));
                c2 = 0.5f * c2 * (1.f + erff(c2 * 0.70710678118654752f));
                c3 = 0.5f * c3 * (1.f + erff(c3 * 0.70710678118654752f));
            }
            if (Cf) {
                float2 o01; o01.x = c0; o01.y = c1;
                float2 o23; o23.x = c2; o23.y = c3;
                *(float2*)&Cf[(size_t)row0 * N + col] = o01;
                *(float2*)&Cf[(size_t)(row0 + 8) * N + col] = o23;
            }
            if (Ch) {
                *(__half2*)&Ch[(size_t)row0 * N + col] = __floats2half2_rn(c0, c1);
                *(__half2*)&Ch[(size_t)(row0 + 8) * N + col] = __floats2half2_rn(c2, c3);
            }
        }
    }
}

// ---------------------------------------------------------------------------
// Flash attention, fp16 mma. grid (Nq/64, B*H), 128 threads (4 warps).
// Warp owns 16 q-rows. Q frags in regs; P overwrites Q smem (warp-private
// rows). K consumed without transpose; V via ldmatrix.x2.trans.
// Smem: Qs/Ps, Ks, Vs : 64 x 72 halves each = 27648 B.
// ---------------------------------------------------------------------------
#define AS_H 72          // halves stride
#define AS_U 36          // u32 stride
#define ATTN_SMEM (3 * 64 * AS_H * 2)

__global__ __launch_bounds__(128, 4) void attn_fp16(
    const __half* __restrict__ qkv, __half* __restrict__ out)
{
    __half* Qs = (__half*)g_dynsmem;              // becomes Ps
    __half* Ks = Qs + 64 * AS_H;
    __half* Vs = Ks + 64 * AS_H;
    uint32_t* Qu = (uint32_t*)Qs;
    const uint32_t* Ku = (const uint32_t*)Ks;
    const uint32_t vbase = smem_u32(Vs);

    const int bh = blockIdx.y;
    const int b = bh >> 4;
    const int h = bh & 15;
    const int q0 = blockIdx.x * 64;
    const int tid = threadIdx.x;
    const int wid = tid >> 5;
    const int lane = tid & 31;
    const int gid = lane >> 2;
    const int tig = lane & 3;
    const int row0 = wid * 16 + gid;

    const size_t base = (size_t)b * Nq * (3 * Cq);
    const __half2 sc2 = __float2half2_rn(0.125f);

    // load Q tile (scaled; 0.125 exact in fp16)
#pragma unroll
    for (int i = 0; i < 4; i++) {
        int idx = tid + i * 128;
        int r = idx >> 3;
        int c8 = idx & 7;
        uint4 v = *(const uint4*)&qkv[base + (size_t)(q0 + r) * (3 * Cq) + h * 64 + c8 * 8];
        __half2* hv = (__half2*)&v;
        hv[0] = __hmul2(hv[0], sc2);
        hv[1] = __hmul2(hv[1], sc2);
        hv[2] = __hmul2(hv[2], sc2);
        hv[3] = __hmul2(hv[3], sc2);
        *(uint4*)&Qs[r * AS_H + c8 * 8] = v;
    }
    __syncthreads();

    // Q a-fragments: 4 k-steps of 16
    uint32_t qf[4][4];
#pragma unroll
    for (int ks = 0; ks < 4; ks++) {
        qf[ks][0] = Qu[row0 * AS_U + ks * 8 + tig];
        qf[ks][1] = Qu[(row0 + 8) * AS_U + ks * 8 + tig];
        qf[ks][2] = Qu[row0 * AS_U + ks * 8 + tig + 4];
        qf[ks][3] = Qu[(row0 + 8) * AS_U + ks * 8 + tig + 4];
    }

    float of[8][4];
#pragma unroll
    for (int nt = 0; nt < 8; nt++)
#pragma unroll
        for (int r = 0; r < 4; r++) of[nt][r] = 0.f;
    float m0 = -INFINITY, m1 = -INFINITY, l0 = 0.f, l1 = 0.f;

    for (int kt = 0; kt < Nq; kt += 64) {
        __syncthreads();
        // load K and V tiles (plain copy)
#pragma unroll
        for (int i = 0; i < 4; i++) {
            int idx = tid + i * 128;
            int r = idx >> 3;
            int c8 = idx & 7;
            *(uint4*)&Ks[r * AS_H + c8 * 8] =
                *(const uint4*)&qkv[base + (size_t)(kt + r) * (3 * Cq) + Cq + h * 64 + c8 * 8];
            *(uint4*)&Vs[r * AS_H + c8 * 8] =
                *(const uint4*)&qkv[base + (size_t)(kt + r) * (3 * Cq) + 2 * Cq + h * 64 + c8 * 8];
        }
        __syncthreads();

        // S = Q @ K^T : 8 n-tiles x 4 k-steps
        float sf[8][4];
#pragma unroll
        for (int nt = 0; nt < 8; nt++)
#pragma unroll
            for (int r = 0; r < 4; r++) sf[nt][r] = 0.f;
#pragma unroll
        for (int ks = 0; ks < 4; ks++) {
#pragma unroll
            for (int nt = 0; nt < 8; nt++) {
                uint32_t bfr[2];
                bfr[0] = Ku[(nt * 8 + gid) * AS_U + ks * 8 + tig];
                bfr[1] = Ku[(nt * 8 + gid) * AS_U + ks * 8 + tig + 4];
                MMA_F16(sf[nt], qf[ks], bfr);
            }
        }

        // online softmax (fp32); P -> half into Qs
        float mx0 = -INFINITY, mx1 = -INFINITY;
#pragma unroll
        for (int nt = 0; nt < 8; nt++) {
            mx0 = fmaxf(mx0, fmaxf(sf[nt][0], sf[nt][1]));
            mx1 = fmaxf(mx1, fmaxf(sf[nt][2], sf[nt][3]));
        }
        mx0 = fmaxf(mx0, __shfl_xor_sync(0xffffffffu, mx0, 1));
        mx0 = fmaxf(mx0, __shfl_xor_sync(0xffffffffu, mx0, 2));
        mx1 = fmaxf(mx1, __shfl_xor_sync(0xffffffffu, mx1, 1));
        mx1 = fmaxf(mx1, __shfl_xor_sync(0xffffffffu, mx1, 2));
        const float mn0 = fmaxf(m0, mx0);
        const float mn1 = fmaxf(m1, mx1);
        const float cr0 = __expf(m0 - mn0);
        const float cr1 = __expf(m1 - mn1);
        float rs0 = 0.f, rs1 = 0.f;
#pragma unroll
        for (int nt = 0; nt < 8; nt++) {
            float p0 = __expf(sf[nt][0] - mn0);
            float p1 = __expf(sf[nt][1] - mn0);
            float p2 = __expf(sf[nt][2] - mn1);
            float p3 = __expf(sf[nt][3] - mn1);
            rs0 += p0 + p1;
            rs1 += p2 + p3;
            *(__half2*)&Qu[row0 * AS_U + nt * 4 + tig] = __floats2half2_rn(p0, p1);
            *(__half2*)&Qu[(row0 + 8) * AS_U + nt * 4 + tig] = __floats2half2_rn(p2, p3);
            of[nt][0] *= cr0; of[nt][1] *= cr0;
            of[nt][2] *= cr1; of[nt][3] *= cr1;
        }
        rs0 += __shfl_xor_sync(0xffffffffu, rs0, 1);
        rs0 += __shfl_xor_sync(0xffffffffu, rs0, 2);
        rs1 += __shfl_xor_sync(0xffffffffu, rs1, 1);
        rs1 += __shfl_xor_sync(0xffffffffu, rs1, 2);
        m0 = mn0; m1 = mn1;
        l0 = l0 * cr0 + rs0;
        l1 = l1 * cr1 + rs1;
        __syncwarp();

        // O += P @ V : 4 key-steps (16 keys) x 8 d-tiles; V via ldmatrix.trans
        const int rl = lane & 15;
#pragma unroll
        for (int ks = 0; ks < 4; ks++) {
            uint32_t pf[4];
            pf[0] = Qu[row0 * AS_U + ks * 8 + tig];
            pf[1] = Qu[(row0 + 8) * AS_U + ks * 8 + tig];
            pf[2] = Qu[row0 * AS_U + ks * 8 + tig + 4];
            pf[3] = Qu[(row0 + 8) * AS_U + ks * 8 + tig + 4];
#pragma unroll
            for (int nt = 0; nt < 8; nt++) {
                uint32_t b0, b1;
                uint32_t addr = vbase + (uint32_t)(((ks * 16 + rl) * AS_H + nt * 8) * 2);
                asm volatile(
                    "ldmatrix.sync.aligned.m8n8.x2.trans.shared.b16 {%0,%1}, [%2];"
                    : "=r"(b0), "=r"(b1) : "r"(addr));
                uint32_t bfr[2] = {b0, b1};
                MMA_F16(of[nt], pf, bfr);
            }
        }
        __syncwarp();
    }

    // epilogue: normalize, half2 stores
    const float inv0 = 1.f / l0;
    const float inv1 = 1.f / l1;
    const size_t grow0 = (size_t)b * Nq + q0 + row0;
#pragma unroll
    for (int nt = 0; nt < 8; nt++) {
        const int col = h * 64 + nt * 8 + tig * 2;
        *(__half2*)&out[grow0 * Cq + col] =
            __floats2half2_rn(of[nt][0] * inv0, of[nt][1] * inv0);
        *(__half2*)&out[(grow0 + 8) * Cq + col] =
            __floats2half2_rn(of[nt][2] * inv1, of[nt][3] * inv1);
    }
}

// ---------------------------------------------------------------------------
// fp32 -> half copy (8 elems/thread)
// ---------------------------------------------------------------------------
__global__ __launch_bounds__(256) void to_half(
    const float* __restrict__ in, __half* __restrict__ out)
{
    const size_t i = ((size_t)blockIdx.x * 256 + threadIdx.x) * 8;
    float4 v0 = *(const float4*)&in[i];
    float4 v1 = *(const float4*)&in[i + 4];
    uint4 o;
    *(__half2*)&o.x = __floats2half2_rn(v0.x, v0.y);
    *(__half2*)&o.y = __floats2half2_rn(v0.z, v0.w);
    *(__half2*)&o.z = __floats2half2_rn(v1.x, v1.y);
    *(__half2*)&o.w = __floats2half2_rn(v1.z, v1.w);
    *(uint4*)&out[i] = o;
}

// ---------------------------------------------------------------------------
// transpose + fp16 convert: out[n][k] = half(in[k][n])
// ---------------------------------------------------------------------------
__global__ __launch_bounds__(256) void transpose_half(
    const float* __restrict__ in, __half* __restrict__ out, int K, int N)
{
    __shared__ float t[32][33];
    const int n0 = blockIdx.x * 32, k0 = blockIdx.y * 32;
    const int tx = threadIdx.x, ty = threadIdx.y;
#pragma unroll
    for (int i = 0; i < 4; i++)
        t[ty + i * 8][tx] = in[(size_t)(k0 + ty + i * 8) * N + n0 + tx];
    __syncthreads();
#pragma unroll
    for (int i = 0; i < 4; i++)
        out[(size_t)(n0 + ty + i * 8) * K + k0 + tx] = __float2half_rn(t[tx][ty + i * 8]);
}

// ---------------------------------------------------------------------------
// out = res + LayerNorm(in)*g + b ; optional half copy of out
// ---------------------------------------------------------------------------
__global__ __launch_bounds__(256) void ln_add_kernel(
    const float* __restrict__ in, const float* __restrict__ res,
    const float* __restrict__ g, const float* __restrict__ bt,
    float* __restrict__ out, __half* __restrict__ outh)
{
    const int row = blockIdx.x;
    const int tid = threadIdx.x;
    const size_t off = (size_t)row * Cq + tid * 4;

    float4 v = *(const float4*)&in[off];
    float s = v.x + v.y + v.z + v.w;
    float ss = v.x * v.x + v.y * v.y + v.z * v.z + v.w * v.w;

#pragma unroll
    for (int o2 = 16; o2 > 0; o2 >>= 1) {
        s  += __shfl_xor_sync(0xffffffffu, s,  o2);
        ss += __shfl_xor_sync(0xffffffffu, ss, o2);
    }
    __shared__ float sh_s[8], sh_ss[8], red[2];
    if ((tid & 31) == 0) { sh_s[tid >> 5] = s; sh_ss[tid >> 5] = ss; }
    __syncthreads();
    if (tid < 32) {
        float a  = (tid < 8) ? sh_s[tid]  : 0.f;
        float a2 = (tid < 8) ? sh_ss[tid] : 0.f;
#pragma unroll
        for (int o2 = 4; o2 > 0; o2 >>= 1) {
            a  += __shfl_xor_sync(0xffffffffu, a,  o2);
            a2 += __shfl_xor_sync(0xffffffffu, a2, o2);
        }
        if (tid == 0) {
            float mean = a * (1.f / Cq);
            float var = a2 * (1.f / Cq) - mean * mean;
            red[0] = mean;
            red[1] = rsqrtf(var + EPSLN);
        }
    }
    __syncthreads();
    float mean = red[0], inv = red[1];

    float4 gv = *(const float4*)&g[tid * 4];
    float4 bv = *(const float4*)&bt[tid * 4];
    float4 rv = *(const float4*)&res[off];
    float4 o;
    o.x = rv.x + (v.x - mean) * inv * gv.x + bv.x;
    o.y = rv.y + (v.y - mean) * inv * gv.y + bv.y;
    o.z = rv.z + (v.z - mean) * inv * gv.z + bv.z;
    o.w = rv.w + (v.w - mean) * inv * gv.w + bv.w;
    *(float4*)&out[off] = o;
    if (outh) {
        uint2 ho;
        *(__half2*)&ho.x = __floats2half2_rn(o.x, o.y);
        *(__half2*)&ho.y = __floats2half2_rn(o.z, o.w);
        *(uint2*)&outh[off] = ho;
    }
}

// ---------------------------------------------------------------------------
// host launcher
// ---------------------------------------------------------------------------
extern "C" void kernel_launch(void* const* d_in, const int* in_sizes, int n_in,
                              void* d_out, int out_size)
{
    const float* x      = (const float*)d_in[0];
    const float* qkv_w  = (const float*)d_in[1];
    const float* qkv_b  = (const float*)d_in[2];
    const float* proj_w = (const float*)d_in[3];
    const float* proj_b = (const float*)d_in[4];
    const float* n1_g   = (const float*)d_in[5];
    const float* n1_b   = (const float*)d_in[6];
    const float* fc1_w  = (const float*)d_in[7];
    const float* fc1_b  = (const float*)d_in[8];
    const float* fc2_w  = (const float*)d_in[9];
    const float* fc2_b  = (const float*)d_in[10];
    const float* n2_g   = (const float*)d_in[11];
    const float* n2_b   = (const float*)d_in[12];
    float* out = (float*)d_out;

    static __half *p_xh = nullptr, *p_qkvh, *p_atth, *p_y1h, *p_h1h,
                  *p_wqkv, *p_wproj, *p_wfc1, *p_wfc2;
    static float *p_a, *p_y1, *p_h2;
    if (!p_xh) {
        cudaGetSymbolAddress((void**)&p_xh,   g_xh);
        cudaGetSymbolAddress((void**)&p_qkvh, g_qkvh);
        cudaGetSymbolAddress((void**)&p_atth, g_atth);
        cudaGetSymbolAddress((void**)&p_a,    g_a);
        cudaGetSymbolAddress((void**)&p_y1,   g_y1);
        cudaGetSymbolAddress((void**)&p_y1h,  g_y1h);
        cudaGetSymbolAddress((void**)&p_h1h,  g_h1h);
        cudaGetSymbolAddress((void**)&p_h2,   g_h2);
        cudaGetSymbolAddress((void**)&p_wqkv, g_wqkvT);
        cudaGetSymbolAddress((void**)&p_wproj, g_wprojT);
        cudaGetSymbolAddress((void**)&p_wfc1, g_wfc1T);
        cudaGetSymbolAddress((void**)&p_wfc2, g_wfc2T);
        cudaFuncSetAttribute(gemm_fp16, cudaFuncAttributeMaxDynamicSharedMemorySize, GEMM_SMEM);
        cudaFuncSetAttribute(attn_fp16, cudaFuncAttributeMaxDynamicSharedMemorySize, ATTN_SMEM);
    }

    // 0) convert x -> half; transpose+convert weights -> half [N][K]
    to_half<<<Mrows * Cq / 2048, 256>>>(x, p_xh);
    transpose_half<<<dim3(3 * Cq / 32, Cq / 32), dim3(32, 8)>>>(qkv_w, p_wqkv, Cq, 3 * Cq);
    transpose_half<<<dim3(Cq / 32, Cq / 32), dim3(32, 8)>>>(proj_w, p_wproj, Cq, Cq);
    transpose_half<<<dim3(4 * Cq / 32, Cq / 32), dim3(32, 8)>>>(fc1_w, p_wfc1, Cq, 4 * Cq);
    transpose_half<<<dim3(Cq / 32, 4 * Cq / 32), dim3(32, 8)>>>(fc2_w, p_wfc2, 4 * Cq, Cq);

    // 1) qkv = x @ qkv_w + qkv_b  -> half
    gemm_fp16<<<dim3(3 * Cq / 128, Mrows / 128), 256, GEMM_SMEM>>>(
        p_xh, p_wqkv, qkv_b, nullptr, p_qkvh, 3 * Cq, Cq, 0);

    // 2) attention -> half
    attn_fp16<<<dim3(Nq / 64, Bq * 16), 128, ATTN_SMEM>>>(p_qkvh, p_atth);

    // 3) a = att @ proj_w + proj_b -> fp32
    gemm_fp16<<<dim3(Cq / 128, Mrows / 128), 256, GEMM_SMEM>>>(
        p_atth, p_wproj, proj_b, p_a, nullptr, Cq, Cq, 0);

    // 4) y1 = a + LN(a) -> fp32 + half
    ln_add_kernel<<<Mrows, 256>>>(p_a, p_a, n1_g, n1_b, p_y1, p_y1h);

    // 5) h1 = GELU(y1 @ fc1_w + fc1_b) -> half
    gemm_fp16<<<dim3(4 * Cq / 128, Mrows / 128), 256, GEMM_SMEM>>>(
        p_y1h, p_wfc1, fc1_b, nullptr, p_h1h, 4 * Cq, Cq, 1);

    // 6) h2 = h1 @ fc2_w + fc2_b -> fp32
    gemm_fp16<<<dim3(Cq / 128, Mrows / 128), 256, GEMM_SMEM>>>(
        p_h1h, p_wfc2, fc2_b, p_h2, nullptr, Cq, 4 * Cq, 0);

    // 7) out = y1 + LN(h2)
    ln_add_kernel<<<Mrows, 256>>>(p_h2, p_y1, n2_g, n2_b, out, nullptr);
}

// round 7
// speedup vs baseline: 5.9630x; 1.1362x over previous
#include <cuda_runtime.h>
#include <cuda_fp16.h>
#include <math.h>
#include <stdint.h>

// ---------------------------------------------------------------------------
// ViT block, all matmul on mma.sync fp16 (fp32 accumulate).
//   qkv = x @ qkv_w + qkv_b            (gemm_fp16 -> half)
//   flash-attention per (b,h)          (attn_fp16: fp16 mma, fp32 softmax,
//                                       cp.async double-buffered K/V, ldmatrix)
//   a  = att @ proj_w + proj_b         (gemm_fp16 -> fp32)
//   y1 = a + LN(a; n1)                 (ln_add -> fp32 + half)
//   h1 = GELU(y1 @ fc1_w + fc1_b)      (gemm_fp16 -> half)
//   h2 = h1 @ fc2_w + fc2_b            (gemm_fp16 -> fp32)
//   out = y1 + LN(h2; n2)              (ln_add -> fp32)
// ---------------------------------------------------------------------------

#define Bq   8
#define Nq   1024
#define Cq   1024
#define Mrows (Bq*Nq)          // 8192
#define EPSLN 1e-6f

// Scratch (static device memory)
__device__ __half g_xh  [Mrows * Cq];
__device__ __half g_qkvh[Mrows * 3 * Cq];
__device__ __half g_atth[Mrows * Cq];
__device__ float  g_a   [Mrows * Cq];
__device__ float  g_y1  [Mrows * Cq];
__device__ __half g_y1h [Mrows * Cq];
__device__ __half g_h1h [Mrows * 4 * Cq];
__device__ float  g_h2  [Mrows * Cq];
__device__ __half g_wqkvT[3 * Cq * Cq];
__device__ __half g_wprojT[Cq * Cq];
__device__ __half g_wfc1T[4 * Cq * Cq];
__device__ __half g_wfc2T[Cq * 4 * Cq];

__device__ __forceinline__ uint32_t smem_u32(const void* p) {
    uint32_t a;
    asm("{ .reg .u64 t; cvta.to.shared.u64 t, %1; cvt.u32.u64 %0, t; }" : "=r"(a) : "l"(p));
    return a;
}

#define MMA_F16(d, a, b)                                                   \
    asm volatile(                                                          \
        "mma.sync.aligned.m16n8k16.row.col.f32.f16.f16.f32 "               \
        "{%0,%1,%2,%3}, {%4,%5,%6,%7}, {%8,%9}, {%0,%1,%2,%3};"            \
        : "+f"(d[0]), "+f"(d[1]), "+f"(d[2]), "+f"(d[3])                   \
        : "r"(a[0]), "r"(a[1]), "r"(a[2]), "r"(a[3]), "r"(b[0]), "r"(b[1]))

#define LDSM_X4(r0, r1, r2, r3, addr)                                      \
    asm volatile("ldmatrix.sync.aligned.m8n8.x4.shared.b16 {%0,%1,%2,%3}, [%4];" \
                 : "=r"(r0), "=r"(r1), "=r"(r2), "=r"(r3) : "r"(addr))

#define CP_ASYNC16(dst, src) \
    asm volatile("cp.async.cg.shared.global [%0], [%1], 16;" :: "r"(dst), "l"(src))
#define CP_COMMIT() asm volatile("cp.async.commit_group;" ::: "memory")
#define CP_WAIT(n)  asm volatile("cp.async.wait_group %0;" :: "n"(n) : "memory")

extern __shared__ __align__(16) char g_dynsmem[];

// ---------------------------------------------------------------------------
// fp16 mma GEMM: C[M,N] = A[M,K] @ Bt[N,K]^T + bias (+GELU).
// 128x128 tile, BK=32, 4-stage cp.async, 256 threads (8 warps, 64x32 tiles).
// Fragments via ldmatrix.x4. Stage: A 128x40h + B 128x40h = 20480 B.
// ---------------------------------------------------------------------------
#define GEMM_SMEM 81920

__global__ __launch_bounds__(256, 2) void gemm_fp16(
    const __half* __restrict__ A, const __half* __restrict__ Bt,
    const float* __restrict__ bias, float* __restrict__ Cf,
    __half* __restrict__ Ch, int N, int K, int gelu)
{
    const uint32_t smu = smem_u32(g_dynsmem);

    const int tid  = threadIdx.x;
    const int lane = tid & 31;
    const int warp = tid >> 5;
    const int gid  = lane >> 2;
    const int tig  = lane & 3;
    const int wm   = (warp >> 2) * 64;
    const int wn   = (warp & 3) * 32;
    const int bm   = blockIdx.y * 128;
    const int bn   = blockIdx.x * 128;

    const int c1 = tid + 256;
    const int r0 = tid >> 2, q0c = (tid & 3);
    const int r1 = c1 >> 2,  q1c = (c1 & 3);

    // ldmatrix per-lane address components (bytes, within stage)
    // A (a-frag): mat0=[m..7]@k0, mat1=[m+8..]@k0, mat2=[m..7]@k8, mat3=[m+8..]@k8
    const int lrowA = ((lane >> 3) & 1) * 8 + (lane & 7);
    const int lcolA = (lane >> 4) * 8;                 // halves
    // B (b-frag pair): mat0=[n..7]@k0, mat1=[n..7]@k8, mat2=[n+8..]@k0, mat3=[n+8..]@k8
    const int lrowB = ((lane >> 4) & 1) * 8 + (lane & 7);
    const int lcolB = ((lane >> 3) & 1) * 8;
    const uint32_t aoff = (uint32_t)(((wm + lrowA) * 40 + lcolA) * 2);
    const uint32_t boff = (uint32_t)(10240 + ((wn + lrowB) * 40 + lcolB) * 2);

    float acc[4][4][4];
#pragma unroll
    for (int mt = 0; mt < 4; mt++)
#pragma unroll
        for (int nt = 0; nt < 4; nt++)
#pragma unroll
            for (int r = 0; r < 4; r++) acc[mt][nt][r] = 0.f;

    const int T = K >> 5;

#define GEMM_ISSUE(t)                                                            \
    do {                                                                         \
        const uint32_t sb_ = smu + (uint32_t)(((t) & 3) * 20480);                \
        CP_ASYNC16(sb_ + r0 * 80 + q0c * 16, &A[(size_t)(bm + r0) * K + (t) * 32 + q0c * 8]); \
        CP_ASYNC16(sb_ + r1 * 80 + q1c * 16, &A[(size_t)(bm + r1) * K + (t) * 32 + q1c * 8]); \
        CP_ASYNC16(sb_ + 10240 + r0 * 80 + q0c * 16, &Bt[(size_t)(bn + r0) * K + (t) * 32 + q0c * 8]); \
        CP_ASYNC16(sb_ + 10240 + r1 * 80 + q1c * 16, &Bt[(size_t)(bn + r1) * K + (t) * 32 + q1c * 8]); \
        CP_COMMIT();                                                             \
    } while (0)

    GEMM_ISSUE(0); GEMM_ISSUE(1); GEMM_ISSUE(2);

    for (int t = 0; t < T; t++) {
        if (t < T - 2)      { CP_WAIT(2); }
        else if (t == T - 2){ CP_WAIT(1); }
        else                { CP_WAIT(0); }
        __syncthreads();
        if (t + 3 < T) GEMM_ISSUE(t + 3);

        const uint32_t sb = smu + (uint32_t)((t & 3) * 20480);
#pragma unroll
        for (int ks = 0; ks < 2; ks++) {
            uint32_t afr[4][4], bfr[4][2];
#pragma unroll
            for (int mt = 0; mt < 4; mt++)
                LDSM_X4(afr[mt][0], afr[mt][1], afr[mt][2], afr[mt][3],
                        sb + aoff + (uint32_t)(mt * 1280 + ks * 32));
#pragma unroll
            for (int ntp = 0; ntp < 2; ntp++)
                LDSM_X4(bfr[2 * ntp][0], bfr[2 * ntp][1],
                        bfr[2 * ntp + 1][0], bfr[2 * ntp + 1][1],
                        sb + boff + (uint32_t)(ntp * 1280 + ks * 32));
#pragma unroll
            for (int mt = 0; mt < 4; mt++)
#pragma unroll
                for (int nt = 0; nt < 4; nt++)
                    MMA_F16(acc[mt][nt], afr[mt], bfr[nt]);
        }
    }
#undef GEMM_ISSUE

#pragma unroll
    for (int mt = 0; mt < 4; mt++) {
        const int row0 = bm + wm + mt * 16 + gid;
#pragma unroll
        for (int nt = 0; nt < 4; nt++) {
            const int col = bn + wn + nt * 8 + tig * 2;
            float2 bv = *(const float2*)&bias[col];
            float c0 = acc[mt][nt][0] + bv.x;
            float c1 = acc[mt][nt][1] + bv.y;
            float c2 = acc[mt][nt][2] + bv.x;
            float c3 = acc[mt][nt][3] + bv.y;
            if (gelu) {
                c0 = 0.5f * c0 * (1.f + erff(c0 * 0.70710678118654752f));
                c1 = 0.5f * c1 * (1.f + erff(c1 * 0.70710678118654752f));
                c2 = 0.5f * c2 * (1.f + erff(c2 * 0.70710678118654752f));
                c3 = 0.5f * c3 * (1.f + erff(c3 * 0.70710678118654752f));
            }
            if (Cf) {
                float2 o01; o01.x = c0; o01.y = c1;
                float2 o23; o23.x = c2; o23.y = c3;
                *(float2*)&Cf[(size_t)row0 * N + col] = o01;
                *(float2*)&Cf[(size_t)(row0 + 8) * N + col] = o23;
            }
            if (Ch) {
                *(__half2*)&Ch[(size_t)row0 * N + col] = __floats2half2_rn(c0, c1);
                *(__half2*)&Ch[(size_t)(row0 + 8) * N + col] = __floats2half2_rn(c2, c3);
            }
        }
    }
}

// ---------------------------------------------------------------------------
// Flash attention, fp16 mma, cp.async double-buffered K/V, ldmatrix frags.
// grid (Nq/64, B*H), 128 threads (4 warps, 16 q-rows each).
// Smem halves: Qs/Ps 64x72 | K0 | K1 | V0 | V1 (each 64x72) = 46080 B.
// ---------------------------------------------------------------------------
#define AS_H 72
#define ATTN_SMEM (5 * 64 * AS_H * 2)

__global__ __launch_bounds__(128, 4) void attn_fp16(
    const __half* __restrict__ qkv, __half* __restrict__ out)
{
    __half* Qs = (__half*)g_dynsmem;
    const uint32_t qbase = smem_u32(Qs);
    const uint32_t kbase0 = qbase + 64 * AS_H * 2;
    const uint32_t vbase0 = qbase + 3 * 64 * AS_H * 2;   // V buffers after K0,K1

    const int bh = blockIdx.y;
    const int b = bh >> 4;
    const int h = bh & 15;
    const int q0 = blockIdx.x * 64;
    const int tid = threadIdx.x;
    const int wid = tid >> 5;
    const int lane = tid & 31;
    const int gid = lane >> 2;
    const int tig = lane & 3;
    const int row0 = wid * 16 + gid;

    const size_t base = (size_t)b * Nq * (3 * Cq);
    const __half2 sc2 = __float2half2_rn(0.125f);

    // ldmatrix lane address components
    const int lrowA = ((lane >> 3) & 1) * 8 + (lane & 7);   // a-frag (Q, P)
    const int lcolA = (lane >> 4) * 8;
    const int lrowB = ((lane >> 4) & 1) * 8 + (lane & 7);   // b-frag (K)
    const int lcolB = ((lane >> 3) & 1) * 8;
    const uint32_t qoff = (uint32_t)(((wid * 16 + lrowA) * AS_H + lcolA) * 2);
    const uint32_t koff = (uint32_t)((lrowB * AS_H + lcolB) * 2);

    // copy-load coordinates (4 x 16B per thread per tensor)
    const int cr = tid >> 3;          // 0..15 (x4 -> rows)
    const int cc8 = tid & 7;          // 16B chunk in row

    // load Q tile (scaled)
#pragma unroll
    for (int i = 0; i < 4; i++) {
        int idx = tid + i * 128;
        int r = idx >> 3;
        int c8 = idx & 7;
        uint4 v = *(const uint4*)&qkv[base + (size_t)(q0 + r) * (3 * Cq) + h * 64 + c8 * 8];
        __half2* hv = (__half2*)&v;
        hv[0] = __hmul2(hv[0], sc2);
        hv[1] = __hmul2(hv[1], sc2);
        hv[2] = __hmul2(hv[2], sc2);
        hv[3] = __hmul2(hv[3], sc2);
        *(uint4*)&Qs[r * AS_H + c8 * 8] = v;
    }

#define ATTN_ISSUE(t)                                                            \
    do {                                                                         \
        const uint32_t kb_ = kbase0 + (uint32_t)(((t) & 1) * 64 * AS_H * 2);     \
        const uint32_t vb_ = vbase0 + (uint32_t)(((t) & 1) * 64 * AS_H * 2);     \
        _Pragma("unroll")                                                        \
        for (int i_ = 0; i_ < 4; i_++) {                                         \
            const int r_ = cr + i_ * 16;                                         \
            const size_t src_ = base + (size_t)((t) * 64 + r_) * (3 * Cq) + h * 64 + cc8 * 8; \
            CP_ASYNC16(kb_ + (r_ * AS_H + cc8 * 8) * 2, &qkv[src_ + Cq]);        \
            CP_ASYNC16(vb_ + (r_ * AS_H + cc8 * 8) * 2, &qkv[src_ + 2 * Cq]);    \
        }                                                                        \
        CP_COMMIT();                                                             \
    } while (0)

    ATTN_ISSUE(0);
    __syncthreads();

    // Q a-fragments: 4 k-steps of 16
    uint32_t qf[4][4];
#pragma unroll
    for (int ks = 0; ks < 4; ks++)
        LDSM_X4(qf[ks][0], qf[ks][1], qf[ks][2], qf[ks][3], qbase + qoff + ks * 32);

    float of[8][4];
#pragma unroll
    for (int nt = 0; nt < 8; nt++)
#pragma unroll
        for (int r = 0; r < 4; r++) of[nt][r] = 0.f;
    float m0 = -INFINITY, m1 = -INFINITY, l0 = 0.f, l1 = 0.f;

    const int TT = Nq / 64;
    for (int t = 0; t < TT; t++) {
        CP_WAIT(0);
        __syncthreads();
        if (t + 1 < TT) ATTN_ISSUE(t + 1);

        const uint32_t kb = kbase0 + (uint32_t)((t & 1) * 64 * AS_H * 2);
        const uint32_t vb = vbase0 + (uint32_t)((t & 1) * 64 * AS_H * 2);

        // S = Q @ K^T : 8 n-tiles (4 ldmatrix.x4 pairs) x 4 k-steps
        float sf[8][4];
#pragma unroll
        for (int nt = 0; nt < 8; nt++)
#pragma unroll
            for (int r = 0; r < 4; r++) sf[nt][r] = 0.f;
#pragma unroll
        for (int ks = 0; ks < 4; ks++) {
#pragma unroll
            for (int ntp = 0; ntp < 4; ntp++) {
                uint32_t b0, b1, b2, b3;
                LDSM_X4(b0, b1, b2, b3, kb + koff + (uint32_t)(ntp * 16 * AS_H * 2 + ks * 32));
                uint32_t f0[2] = {b0, b1};
                uint32_t f1[2] = {b2, b3};
                MMA_F16(sf[2 * ntp], qf[ks], f0);
                MMA_F16(sf[2 * ntp + 1], qf[ks], f1);
            }
        }

        // online softmax (fp32); P -> half into Qs (warp-private rows)
        float mx0 = -INFINITY, mx1 = -INFINITY;
#pragma unroll
        for (int nt = 0; nt < 8; nt++) {
            mx0 = fmaxf(mx0, fmaxf(sf[nt][0], sf[nt][1]));
            mx1 = fmaxf(mx1, fmaxf(sf[nt][2], sf[nt][3]));
        }
        mx0 = fmaxf(mx0, __shfl_xor_sync(0xffffffffu, mx0, 1));
        mx0 = fmaxf(mx0, __shfl_xor_sync(0xffffffffu, mx0, 2));
        mx1 = fmaxf(mx1, __shfl_xor_sync(0xffffffffu, mx1, 1));
        mx1 = fmaxf(mx1, __shfl_xor_sync(0xffffffffu, mx1, 2));
        const float mn0 = fmaxf(m0, mx0);
        const float mn1 = fmaxf(m1, mx1);
        const float cr0 = __expf(m0 - mn0);
        const float cr1 = __expf(m1 - mn1);
        float rs0 = 0.f, rs1 = 0.f;
#pragma unroll
        for (int nt = 0; nt < 8; nt++) {
            float p0 = __expf(sf[nt][0] - mn0);
            float p1 = __expf(sf[nt][1] - mn0);
            float p2 = __expf(sf[nt][2] - mn1);
            float p3 = __expf(sf[nt][3] - mn1);
            rs0 += p0 + p1;
            rs1 += p2 + p3;
            *(__half2*)&Qs[row0 * AS_H + nt * 8 + tig * 2] = __floats2half2_rn(p0, p1);
            *(__half2*)&Qs[(row0 + 8) * AS_H + nt * 8 + tig * 2] = __floats2half2_rn(p2, p3);
            of[nt][0] *= cr0; of[nt][1] *= cr0;
            of[nt][2] *= cr1; of[nt][3] *= cr1;
        }
        rs0 += __shfl_xor_sync(0xffffffffu, rs0, 1);
        rs0 += __shfl_xor_sync(0xffffffffu, rs0, 2);
        rs1 += __shfl_xor_sync(0xffffffffu, rs1, 1);
        rs1 += __shfl_xor_sync(0xffffffffu, rs1, 2);
        m0 = mn0; m1 = mn1;
        l0 = l0 * cr0 + rs0;
        l1 = l1 * cr1 + rs1;
        __syncwarp();

        // O += P @ V : 4 key-steps x 8 d-tiles; P via ldmatrix.x4, V via x2.trans
        const int rl = lane & 15;
#pragma unroll
        for (int ks = 0; ks < 4; ks++) {
            uint32_t pf[4];
            LDSM_X4(pf[0], pf[1], pf[2], pf[3], qbase + qoff + (uint32_t)(ks * 32));
#pragma unroll
            for (int nt = 0; nt < 8; nt++) {
                uint32_t b0, b1;
                uint32_t addr = vb + (uint32_t)(((ks * 16 + rl) * AS_H + nt * 8) * 2);
                asm volatile(
                    "ldmatrix.sync.aligned.m8n8.x2.trans.shared.b16 {%0,%1}, [%2];"
                    : "=r"(b0), "=r"(b1) : "r"(addr));
                uint32_t bfr[2] = {b0, b1};
                MMA_F16(of[nt], pf, bfr);
            }
        }
        __syncwarp();
    }
#undef ATTN_ISSUE

    // epilogue: normalize, half2 stores
    const float inv0 = 1.f / l0;
    const float inv1 = 1.f / l1;
    const size_t grow0 = (size_t)b * Nq + q0 + row0;
#pragma unroll
    for (int nt = 0; nt < 8; nt++) {
        const int col = h * 64 + nt * 8 + tig * 2;
        *(__half2*)&out[grow0 * Cq + col] =
            __floats2half2_rn(of[nt][0] * inv0, of[nt][1] * inv0);
        *(__half2*)&out[(grow0 + 8) * Cq + col] =
            __floats2half2_rn(of[nt][2] * inv1, of[nt][3] * inv1);
    }
}

// ---------------------------------------------------------------------------
// fp32 -> half copy (8 elems/thread)
// ---------------------------------------------------------------------------
__global__ __launch_bounds__(256) void to_half(
    const float* __restrict__ in, __half* __restrict__ out)
{
    const size_t i = ((size_t)blockIdx.x * 256 + threadIdx.x) * 8;
    float4 v0 = *(const float4*)&in[i];
    float4 v1 = *(const float4*)&in[i + 4];
    uint4 o;
    *(__half2*)&o.x = __floats2half2_rn(v0.x, v0.y);
    *(__half2*)&o.y = __floats2half2_rn(v0.z, v0.w);
    *(__half2*)&o.z = __floats2half2_rn(v1.x, v1.y);
    *(__half2*)&o.w = __floats2half2_rn(v1.z, v1.w);
    *(uint4*)&out[i] = o;
}

// ---------------------------------------------------------------------------
// transpose + fp16 convert: out[n][k] = half(in[k][n])
// ---------------------------------------------------------------------------
__global__ __launch_bounds__(256) void transpose_half(
    const float* __restrict__ in, __half* __restrict__ out, int K, int N)
{
    __shared__ float t[32][33];
    const int n0 = blockIdx.x * 32, k0 = blockIdx.y * 32;
    const int tx = threadIdx.x, ty = threadIdx.y;
#pragma unroll
    for (int i = 0; i < 4; i++)
        t[ty + i * 8][tx] = in[(size_t)(k0 + ty + i * 8) * N + n0 + tx];
    __syncthreads();
#pragma unroll
    for (int i = 0; i < 4; i++)
        out[(size_t)(n0 + ty + i * 8) * K + k0 + tx] = __float2half_rn(t[tx][ty + i * 8]);
}

// ---------------------------------------------------------------------------
// out = res + LayerNorm(in)*g + b ; optional half copy of out
// ---------------------------------------------------------------------------
__global__ __launch_bounds__(256) void ln_add_kernel(
    const float* __restrict__ in, const float* __restrict__ res,
    const float* __restrict__ g, const float* __restrict__ bt,
    float* __restrict__ out, __half* __restrict__ outh)
{
    const int row = blockIdx.x;
    const int tid = threadIdx.x;
    const size_t off = (size_t)row * Cq + tid * 4;

    float4 v = *(const float4*)&in[off];
    float s = v.x + v.y + v.z + v.w;
    float ss = v.x * v.x + v.y * v.y + v.z * v.z + v.w * v.w;

#pragma unroll
    for (int o2 = 16; o2 > 0; o2 >>= 1) {
        s  += __shfl_xor_sync(0xffffffffu, s,  o2);
        ss += __shfl_xor_sync(0xffffffffu, ss, o2);
    }
    __shared__ float sh_s[8], sh_ss[8], red[2];
    if ((tid & 31) == 0) { sh_s[tid >> 5] = s; sh_ss[tid >> 5] = ss; }
    __syncthreads();
    if (tid < 32) {
        float a  = (tid < 8) ? sh_s[tid]  : 0.f;
        float a2 = (tid < 8) ? sh_ss[tid] : 0.f;
#pragma unroll
        for (int o2 = 4; o2 > 0; o2 >>= 1) {
            a  += __shfl_xor_sync(0xffffffffu, a,  o2);
            a2 += __shfl_xor_sync(0xffffffffu, a2, o2);
        }
        if (tid == 0) {
            float mean = a * (1.f / Cq);
            float var = a2 * (1.f / Cq) - mean * mean;
            red[0] = mean;
            red[1] = rsqrtf(var + EPSLN);
        }
    }
    __syncthreads();
    float mean = red[0], inv = red[1];

    float4 gv = *(const float4*)&g[tid * 4];
    float4 bv = *(const float4*)&bt[tid * 4];
    float4 rv = *(const float4*)&res[off];
    float4 o;
    o.x = rv.x + (v.x - mean) * inv * gv.x + bv.x;
    o.y = rv.y + (v.y - mean) * inv * gv.y + bv.y;
    o.z = rv.z + (v.z - mean) * inv * gv.z + bv.z;
    o.w = rv.w + (v.w - mean) * inv * gv.w + bv.w;
    *(float4*)&out[off] = o;
    if (outh) {
        uint2 ho;
        *(__half2*)&ho.x = __floats2half2_rn(o.x, o.y);
        *(__half2*)&ho.y = __floats2half2_rn(o.z, o.w);
        *(uint2*)&outh[off] = ho;
    }
}

// ---------------------------------------------------------------------------
// host launcher
// ---------------------------------------------------------------------------
extern "C" void kernel_launch(void* const* d_in, const int* in_sizes, int n_in,
                              void* d_out, int out_size)
{
    const float* x      = (const float*)d_in[0];
    const float* qkv_w  = (const float*)d_in[1];
    const float* qkv_b  = (const float*)d_in[2];
    const float* proj_w = (const float*)d_in[3];
    const float* proj_b = (const float*)d_in[4];
    const float* n1_g   = (const float*)d_in[5];
    const float* n1_b   = (const float*)d_in[6];
    const float* fc1_w  = (const float*)d_in[7];
    const float* fc1_b  = (const float*)d_in[8];
    const float* fc2_w  = (const float*)d_in[9];
    const float* fc2_b  = (const float*)d_in[10];
    const float* n2_g   = (const float*)d_in[11];
    const float* n2_b   = (const float*)d_in[12];
    float* out = (float*)d_out;

    static __half *p_xh = nullptr, *p_qkvh, *p_atth, *p_y1h, *p_h1h,
                  *p_wqkv, *p_wproj, *p_wfc1, *p_wfc2;
    static float *p_a, *p_y1, *p_h2;
    if (!p_xh) {
        cudaGetSymbolAddress((void**)&p_xh,   g_xh);
        cudaGetSymbolAddress((void**)&p_qkvh, g_qkvh);
        cudaGetSymbolAddress((void**)&p_atth, g_atth);
        cudaGetSymbolAddress((void**)&p_a,    g_a);
        cudaGetSymbolAddress((void**)&p_y1,   g_y1);
        cudaGetSymbolAddress((void**)&p_y1h,  g_y1h);
        cudaGetSymbolAddress((void**)&p_h1h,  g_h1h);
        cudaGetSymbolAddress((void**)&p_h2,   g_h2);
        cudaGetSymbolAddress((void**)&p_wqkv, g_wqkvT);
        cudaGetSymbolAddress((void**)&p_wproj, g_wprojT);
        cudaGetSymbolAddress((void**)&p_wfc1, g_wfc1T);
        cudaGetSymbolAddress((void**)&p_wfc2, g_wfc2T);
        cudaFuncSetAttribute(gemm_fp16, cudaFuncAttributeMaxDynamicSharedMemorySize, GEMM_SMEM);
        cudaFuncSetAttribute(attn_fp16, cudaFuncAttributeMaxDynamicSharedMemorySize, ATTN_SMEM);
    }

    // 0) convert x -> half; transpose+convert weights -> half [N][K]
    to_half<<<Mrows * Cq / 2048, 256>>>(x, p_xh);
    transpose_half<<<dim3(3 * Cq / 32, Cq / 32), dim3(32, 8)>>>(qkv_w, p_wqkv, Cq, 3 * Cq);
    transpose_half<<<dim3(Cq / 32, Cq / 32), dim3(32, 8)>>>(proj_w, p_wproj, Cq, Cq);
    transpose_half<<<dim3(4 * Cq / 32, Cq / 32), dim3(32, 8)>>>(fc1_w, p_wfc1, Cq, 4 * Cq);
    transpose_half<<<dim3(Cq / 32, 4 * Cq / 32), dim3(32, 8)>>>(fc2_w, p_wfc2, 4 * Cq, Cq);

    // 1) qkv = x @ qkv_w + qkv_b  -> half
    gemm_fp16<<<dim3(3 * Cq / 128, Mrows / 128), 256, GEMM_SMEM>>>(
        p_xh, p_wqkv, qkv_b, nullptr, p_qkvh, 3 * Cq, Cq, 0);

    // 2) attention -> half
    attn_fp16<<<dim3(Nq / 64, Bq * 16), 128, ATTN_SMEM>>>(p_qkvh, p_atth);

    // 3) a = att @ proj_w + proj_b -> fp32
    gemm_fp16<<<dim3(Cq / 128, Mrows / 128), 256, GEMM_SMEM>>>(
        p_atth, p_wproj, proj_b, p_a, nullptr, Cq, Cq, 0);

    // 4) y1 = a + LN(a) -> fp32 + half
    ln_add_kernel<<<Mrows, 256>>>(p_a, p_a, n1_g, n1_b, p_y1, p_y1h);

    // 5) h1 = GELU(y1 @ fc1_w + fc1_b) -> half
    gemm_fp16<<<dim3(4 * Cq / 128, Mrows / 128), 256, GEMM_SMEM>>>(
        p_y1h, p_wfc1, fc1_b, nullptr, p_h1h, 4 * Cq, Cq, 1);

    // 6) h2 = h1 @ fc2_w + fc2_b -> fp32
    gemm_fp16<<<dim3(Cq / 128, Mrows / 128), 256, GEMM_SMEM>>>(
        p_h1h, p_wfc2, fc2_b, p_h2, nullptr, Cq, 4 * Cq, 0);

    // 7) out = y1 + LN(h2)
    ln_add_kernel<<<Mrows, 256>>>(p_h2, p_y1, n2_g, n2_b, out, nullptr);
}

// round 8
// speedup vs baseline: 6.2864x; 1.0542x over previous
#include <cuda_runtime.h>
#include <cuda_fp16.h>
#include <math.h>
#include <stdint.h>

// ---------------------------------------------------------------------------
// ViT block, all matmul on mma.sync fp16 (fp32 accumulate).
// Two batch-halves run on two forked streams (graph fork/join) to smooth
// wave quantization; weight transposes overlap on a third stream.
//   qkv = x @ qkv_w + qkv_b            (gemm_fp16 -> half)
//   flash-attention per (b,h)          (attn_fp16)
//   a  = att @ proj_w + proj_b         (gemm_fp16 -> fp32)
//   y1 = a + LN(a; n1)                 (ln_add -> fp32 + half)
//   h1 = GELU(y1 @ fc1_w + fc1_b)      (gemm_fp16 -> half)
//   h2 = h1 @ fc2_w + fc2_b            (gemm_fp16 -> fp32)
//   out = y1 + LN(h2; n2)              (ln_add -> fp32)
// ---------------------------------------------------------------------------

#define Bq   8
#define Nq   1024
#define Cq   1024
#define Mrows (Bq*Nq)          // 8192
#define MHALF (Mrows/2)        // 4096 rows per stream-half
#define EPSLN 1e-6f

// Scratch (static device memory)
__device__ __half g_xh  [Mrows * Cq];
__device__ __half g_qkvh[Mrows * 3 * Cq];
__device__ __half g_atth[Mrows * Cq];
__device__ float  g_a   [Mrows * Cq];
__device__ float  g_y1  [Mrows * Cq];
__device__ __half g_y1h [Mrows * Cq];
__device__ __half g_h1h [Mrows * 4 * Cq];
__device__ float  g_h2  [Mrows * Cq];
__device__ __half g_wqkvT[3 * Cq * Cq];
__device__ __half g_wprojT[Cq * Cq];
__device__ __half g_wfc1T[4 * Cq * Cq];
__device__ __half g_wfc2T[Cq * 4 * Cq];

__device__ __forceinline__ uint32_t smem_u32(const void* p) {
    uint32_t a;
    asm("{ .reg .u64 t; cvta.to.shared.u64 t, %1; cvt.u32.u64 %0, t; }" : "=r"(a) : "l"(p));
    return a;
}

#define MMA_F16(d, a, b)                                                   \
    asm volatile(                                                          \
        "mma.sync.aligned.m16n8k16.row.col.f32.f16.f16.f32 "               \
        "{%0,%1,%2,%3}, {%4,%5,%6,%7}, {%8,%9}, {%0,%1,%2,%3};"            \
        : "+f"(d[0]), "+f"(d[1]), "+f"(d[2]), "+f"(d[3])                   \
        : "r"(a[0]), "r"(a[1]), "r"(a[2]), "r"(a[3]), "r"(b[0]), "r"(b[1]))

#define LDSM_X4(r0, r1, r2, r3, addr)                                      \
    asm volatile("ldmatrix.sync.aligned.m8n8.x4.shared.b16 {%0,%1,%2,%3}, [%4];" \
                 : "=r"(r0), "=r"(r1), "=r"(r2), "=r"(r3) : "r"(addr))

#define CP_ASYNC16(dst, src) \
    asm volatile("cp.async.cg.shared.global [%0], [%1], 16;" :: "r"(dst), "l"(src))
#define CP_COMMIT() asm volatile("cp.async.commit_group;" ::: "memory")
#define CP_WAIT(n)  asm volatile("cp.async.wait_group %0;" :: "n"(n) : "memory")

extern __shared__ __align__(16) char g_dynsmem[];

// ---------------------------------------------------------------------------
// fp16 mma GEMM: C[M,N] = A[M,K] @ Bt[N,K]^T + bias (+GELU).
// 128x128 tile, BK=32, 4-stage cp.async, 256 threads (8 warps, 64x32 tiles).
// Fragments via ldmatrix.x4. Stage: A 128x40h + B 128x40h = 20480 B.
// ---------------------------------------------------------------------------
#define GEMM_SMEM 81920

__global__ __launch_bounds__(256, 2) void gemm_fp16(
    const __half* __restrict__ A, const __half* __restrict__ Bt,
    const float* __restrict__ bias, float* __restrict__ Cf,
    __half* __restrict__ Ch, int N, int K, int gelu)
{
    const uint32_t smu = smem_u32(g_dynsmem);

    const int tid  = threadIdx.x;
    const int lane = tid & 31;
    const int warp = tid >> 5;
    const int gid  = lane >> 2;
    const int tig  = lane & 3;
    const int wm   = (warp >> 2) * 64;
    const int wn   = (warp & 3) * 32;
    const int bm   = blockIdx.y * 128;
    const int bn   = blockIdx.x * 128;

    const int c1 = tid + 256;
    const int r0 = tid >> 2, q0c = (tid & 3);
    const int r1 = c1 >> 2,  q1c = (c1 & 3);

    const int lrowA = ((lane >> 3) & 1) * 8 + (lane & 7);
    const int lcolA = (lane >> 4) * 8;
    const int lrowB = ((lane >> 4) & 1) * 8 + (lane & 7);
    const int lcolB = ((lane >> 3) & 1) * 8;
    const uint32_t aoff = (uint32_t)(((wm + lrowA) * 40 + lcolA) * 2);
    const uint32_t boff = (uint32_t)(10240 + ((wn + lrowB) * 40 + lcolB) * 2);

    float acc[4][4][4];
#pragma unroll
    for (int mt = 0; mt < 4; mt++)
#pragma unroll
        for (int nt = 0; nt < 4; nt++)
#pragma unroll
            for (int r = 0; r < 4; r++) acc[mt][nt][r] = 0.f;

    const int T = K >> 5;

#define GEMM_ISSUE(t)                                                            \
    do {                                                                         \
        const uint32_t sb_ = smu + (uint32_t)(((t) & 3) * 20480);                \
        CP_ASYNC16(sb_ + r0 * 80 + q0c * 16, &A[(size_t)(bm + r0) * K + (t) * 32 + q0c * 8]); \
        CP_ASYNC16(sb_ + r1 * 80 + q1c * 16, &A[(size_t)(bm + r1) * K + (t) * 32 + q1c * 8]); \
        CP_ASYNC16(sb_ + 10240 + r0 * 80 + q0c * 16, &Bt[(size_t)(bn + r0) * K + (t) * 32 + q0c * 8]); \
        CP_ASYNC16(sb_ + 10240 + r1 * 80 + q1c * 16, &Bt[(size_t)(bn + r1) * K + (t) * 32 + q1c * 8]); \
        CP_COMMIT();                                                             \
    } while (0)

    GEMM_ISSUE(0); GEMM_ISSUE(1); GEMM_ISSUE(2);

    for (int t = 0; t < T; t++) {
        if (t < T - 2)      { CP_WAIT(2); }
        else if (t == T - 2){ CP_WAIT(1); }
        else                { CP_WAIT(0); }
        __syncthreads();
        if (t + 3 < T) GEMM_ISSUE(t + 3);

        const uint32_t sb = smu + (uint32_t)((t & 3) * 20480);
#pragma unroll
        for (int ks = 0; ks < 2; ks++) {
            uint32_t afr[4][4], bfr[4][2];
#pragma unroll
            for (int mt = 0; mt < 4; mt++)
                LDSM_X4(afr[mt][0], afr[mt][1], afr[mt][2], afr[mt][3],
                        sb + aoff + (uint32_t)(mt * 1280 + ks * 32));
#pragma unroll
            for (int ntp = 0; ntp < 2; ntp++)
                LDSM_X4(bfr[2 * ntp][0], bfr[2 * ntp][1],
                        bfr[2 * ntp + 1][0], bfr[2 * ntp + 1][1],
                        sb + boff + (uint32_t)(ntp * 1280 + ks * 32));
#pragma unroll
            for (int mt = 0; mt < 4; mt++)
#pragma unroll
                for (int nt = 0; nt < 4; nt++)
                    MMA_F16(acc[mt][nt], afr[mt], bfr[nt]);
        }
    }
#undef GEMM_ISSUE

#pragma unroll
    for (int mt = 0; mt < 4; mt++) {
        const int row0 = bm + wm + mt * 16 + gid;
#pragma unroll
        for (int nt = 0; nt < 4; nt++) {
            const int col = bn + wn + nt * 8 + tig * 2;
            float2 bv = *(const float2*)&bias[col];
            float c0 = acc[mt][nt][0] + bv.x;
            float c1 = acc[mt][nt][1] + bv.y;
            float c2 = acc[mt][nt][2] + bv.x;
            float c3 = acc[mt][nt][3] + bv.y;
            if (gelu) {
                c0 = 0.5f * c0 * (1.f + erff(c0 * 0.70710678118654752f));
                c1 = 0.5f * c1 * (1.f + erff(c1 * 0.70710678118654752f));
                c2 = 0.5f * c2 * (1.f + erff(c2 * 0.70710678118654752f));
                c3 = 0.5f * c3 * (1.f + erff(c3 * 0.70710678118654752f));
            }
            if (Cf) {
                float2 o01; o01.x = c0; o01.y = c1;
                float2 o23; o23.x = c2; o23.y = c3;
                *(float2*)&Cf[(size_t)row0 * N + col] = o01;
                *(float2*)&Cf[(size_t)(row0 + 8) * N + col] = o23;
            }
            if (Ch) {
                *(__half2*)&Ch[(size_t)row0 * N + col] = __floats2half2_rn(c0, c1);
                *(__half2*)&Ch[(size_t)(row0 + 8) * N + col] = __floats2half2_rn(c2, c3);
            }
        }
    }
}

// ---------------------------------------------------------------------------
// Flash attention, fp16 mma, cp.async double-buffered K/V, ldmatrix frags.
// grid (Nq/64, nbatch*H), 128 threads (4 warps, 16 q-rows each).
// ---------------------------------------------------------------------------
#define AS_H 72
#define ATTN_SMEM (5 * 64 * AS_H * 2)

__global__ __launch_bounds__(128, 4) void attn_fp16(
    const __half* __restrict__ qkv, __half* __restrict__ out)
{
    __half* Qs = (__half*)g_dynsmem;
    const uint32_t qbase = smem_u32(Qs);
    const uint32_t kbase0 = qbase + 64 * AS_H * 2;
    const uint32_t vbase0 = qbase + 3 * 64 * AS_H * 2;

    const int bh = blockIdx.y;
    const int b = bh >> 4;
    const int h = bh & 15;
    const int q0 = blockIdx.x * 64;
    const int tid = threadIdx.x;
    const int wid = tid >> 5;
    const int lane = tid & 31;
    const int gid = lane >> 2;
    const int tig = lane & 3;
    const int row0 = wid * 16 + gid;

    const size_t base = (size_t)b * Nq * (3 * Cq);
    const __half2 sc2 = __float2half2_rn(0.125f);

    const int lrowA = ((lane >> 3) & 1) * 8 + (lane & 7);
    const int lcolA = (lane >> 4) * 8;
    const int lrowB = ((lane >> 4) & 1) * 8 + (lane & 7);
    const int lcolB = ((lane >> 3) & 1) * 8;
    const uint32_t qoff = (uint32_t)(((wid * 16 + lrowA) * AS_H + lcolA) * 2);
    const uint32_t koff = (uint32_t)((lrowB * AS_H + lcolB) * 2);

    const int cr = tid >> 3;
    const int cc8 = tid & 7;

#pragma unroll
    for (int i = 0; i < 4; i++) {
        int idx = tid + i * 128;
        int r = idx >> 3;
        int c8 = idx & 7;
        uint4 v = *(const uint4*)&qkv[base + (size_t)(q0 + r) * (3 * Cq) + h * 64 + c8 * 8];
        __half2* hv = (__half2*)&v;
        hv[0] = __hmul2(hv[0], sc2);
        hv[1] = __hmul2(hv[1], sc2);
        hv[2] = __hmul2(hv[2], sc2);
        hv[3] = __hmul2(hv[3], sc2);
        *(uint4*)&Qs[r * AS_H + c8 * 8] = v;
    }

#define ATTN_ISSUE(t)                                                            \
    do {                                                                         \
        const uint32_t kb_ = kbase0 + (uint32_t)(((t) & 1) * 64 * AS_H * 2);     \
        const uint32_t vb_ = vbase0 + (uint32_t)(((t) & 1) * 64 * AS_H * 2);     \
        _Pragma("unroll")                                                        \
        for (int i_ = 0; i_ < 4; i_++) {                                         \
            const int r_ = cr + i_ * 16;                                         \
            const size_t src_ = base + (size_t)((t) * 64 + r_) * (3 * Cq) + h * 64 + cc8 * 8; \
            CP_ASYNC16(kb_ + (r_ * AS_H + cc8 * 8) * 2, &qkv[src_ + Cq]);        \
            CP_ASYNC16(vb_ + (r_ * AS_H + cc8 * 8) * 2, &qkv[src_ + 2 * Cq]);    \
        }                                                                        \
        CP_COMMIT();                                                             \
    } while (0)

    ATTN_ISSUE(0);
    __syncthreads();

    uint32_t qf[4][4];
#pragma unroll
    for (int ks = 0; ks < 4; ks++)
        LDSM_X4(qf[ks][0], qf[ks][1], qf[ks][2], qf[ks][3], qbase + qoff + ks * 32);

    float of[8][4];
#pragma unroll
    for (int nt = 0; nt < 8; nt++)
#pragma unroll
        for (int r = 0; r < 4; r++) of[nt][r] = 0.f;
    float m0 = -INFINITY, m1 = -INFINITY, l0 = 0.f, l1 = 0.f;

    const int TT = Nq / 64;
    for (int t = 0; t < TT; t++) {
        CP_WAIT(0);
        __syncthreads();
        if (t + 1 < TT) ATTN_ISSUE(t + 1);

        const uint32_t kb = kbase0 + (uint32_t)((t & 1) * 64 * AS_H * 2);
        const uint32_t vb = vbase0 + (uint32_t)((t & 1) * 64 * AS_H * 2);

        float sf[8][4];
#pragma unroll
        for (int nt = 0; nt < 8; nt++)
#pragma unroll
            for (int r = 0; r < 4; r++) sf[nt][r] = 0.f;
#pragma unroll
        for (int ks = 0; ks < 4; ks++) {
#pragma unroll
            for (int ntp = 0; ntp < 4; ntp++) {
                uint32_t b0, b1, b2, b3;
                LDSM_X4(b0, b1, b2, b3, kb + koff + (uint32_t)(ntp * 16 * AS_H * 2 + ks * 32));
                uint32_t f0[2] = {b0, b1};
                uint32_t f1[2] = {b2, b3};
                MMA_F16(sf[2 * ntp], qf[ks], f0);
                MMA_F16(sf[2 * ntp + 1], qf[ks], f1);
            }
        }

        float mx0 = -INFINITY, mx1 = -INFINITY;
#pragma unroll
        for (int nt = 0; nt < 8; nt++) {
            mx0 = fmaxf(mx0, fmaxf(sf[nt][0], sf[nt][1]));
            mx1 = fmaxf(mx1, fmaxf(sf[nt][2], sf[nt][3]));
        }
        mx0 = fmaxf(mx0, __shfl_xor_sync(0xffffffffu, mx0, 1));
        mx0 = fmaxf(mx0, __shfl_xor_sync(0xffffffffu, mx0, 2));
        mx1 = fmaxf(mx1, __shfl_xor_sync(0xffffffffu, mx1, 1));
        mx1 = fmaxf(mx1, __shfl_xor_sync(0xffffffffu, mx1, 2));
        const float mn0 = fmaxf(m0, mx0);
        const float mn1 = fmaxf(m1, mx1);
        const float cr0 = __expf(m0 - mn0);
        const float cr1 = __expf(m1 - mn1);
        float rs0 = 0.f, rs1 = 0.f;
#pragma unroll
        for (int nt = 0; nt < 8; nt++) {
            float p0 = __expf(sf[nt][0] - mn0);
            float p1 = __expf(sf[nt][1] - mn0);
            float p2 = __expf(sf[nt][2] - mn1);
            float p3 = __expf(sf[nt][3] - mn1);
            rs0 += p0 + p1;
            rs1 += p2 + p3;
            *(__half2*)&Qs[row0 * AS_H + nt * 8 + tig * 2] = __floats2half2_rn(p0, p1);
            *(__half2*)&Qs[(row0 + 8) * AS_H + nt * 8 + tig * 2] = __floats2half2_rn(p2, p3);
            of[nt][0] *= cr0; of[nt][1] *= cr0;
            of[nt][2] *= cr1; of[nt][3] *= cr1;
        }
        rs0 += __shfl_xor_sync(0xffffffffu, rs0, 1);
        rs0 += __shfl_xor_sync(0xffffffffu, rs0, 2);
        rs1 += __shfl_xor_sync(0xffffffffu, rs1, 1);
        rs1 += __shfl_xor_sync(0xffffffffu, rs1, 2);
        m0 = mn0; m1 = mn1;
        l0 = l0 * cr0 + rs0;
        l1 = l1 * cr1 + rs1;
        __syncwarp();

        const int rl = lane & 15;
#pragma unroll
        for (int ks = 0; ks < 4; ks++) {
            uint32_t pf[4];
            LDSM_X4(pf[0], pf[1], pf[2], pf[3], qbase + qoff + (uint32_t)(ks * 32));
#pragma unroll
            for (int nt = 0; nt < 8; nt++) {
                uint32_t b0, b1;
                uint32_t addr = vb + (uint32_t)(((ks * 16 + rl) * AS_H + nt * 8) * 2);
                asm volatile(
                    "ldmatrix.sync.aligned.m8n8.x2.trans.shared.b16 {%0,%1}, [%2];"
                    : "=r"(b0), "=r"(b1) : "r"(addr));
                uint32_t bfr[2] = {b0, b1};
                MMA_F16(of[nt], pf, bfr);
            }
        }
        __syncwarp();
    }
#undef ATTN_ISSUE

    const float inv0 = 1.f / l0;
    const float inv1 = 1.f / l1;
    const size_t grow0 = (size_t)b * Nq + q0 + row0;
#pragma unroll
    for (int nt = 0; nt < 8; nt++) {
        const int col = h * 64 + nt * 8 + tig * 2;
        *(__half2*)&out[grow0 * Cq + col] =
            __floats2half2_rn(of[nt][0] * inv0, of[nt][1] * inv0);
        *(__half2*)&out[(grow0 + 8) * Cq + col] =
            __floats2half2_rn(of[nt][2] * inv1, of[nt][3] * inv1);
    }
}

// ---------------------------------------------------------------------------
// fp32 -> half copy (8 elems/thread)
// ---------------------------------------------------------------------------
__global__ __launch_bounds__(256) void to_half(
    const float* __restrict__ in, __half* __restrict__ out)
{
    const size_t i = ((size_t)blockIdx.x * 256 + threadIdx.x) * 8;
    float4 v0 = *(const float4*)&in[i];
    float4 v1 = *(const float4*)&in[i + 4];
    uint4 o;
    *(__half2*)&o.x = __floats2half2_rn(v0.x, v0.y);
    *(__half2*)&o.y = __floats2half2_rn(v0.z, v0.w);
    *(__half2*)&o.z = __floats2half2_rn(v1.x, v1.y);
    *(__half2*)&o.w = __floats2half2_rn(v1.z, v1.w);
    *(uint4*)&out[i] = o;
}

// ---------------------------------------------------------------------------
// transpose + fp16 convert: out[n][k] = half(in[k][n])
// ---------------------------------------------------------------------------
__global__ __launch_bounds__(256) void transpose_half(
    const float* __restrict__ in, __half* __restrict__ out, int K, int N)
{
    __shared__ float t[32][33];
    const int n0 = blockIdx.x * 32, k0 = blockIdx.y * 32;
    const int tx = threadIdx.x, ty = threadIdx.y;
#pragma unroll
    for (int i = 0; i < 4; i++)
        t[ty + i * 8][tx] = in[(size_t)(k0 + ty + i * 8) * N + n0 + tx];
    __syncthreads();
#pragma unroll
    for (int i = 0; i < 4; i++)
        out[(size_t)(n0 + ty + i * 8) * K + k0 + tx] = __float2half_rn(t[tx][ty + i * 8]);
}

// ---------------------------------------------------------------------------
// out = res + LayerNorm(in)*g + b ; optional half copy of out
// ---------------------------------------------------------------------------
__global__ __launch_bounds__(256) void ln_add_kernel(
    const float* __restrict__ in, const float* __restrict__ res,
    const float* __restrict__ g, const float* __restrict__ bt,
    float* __restrict__ out, __half* __restrict__ outh)
{
    const int row = blockIdx.x;
    const int tid = threadIdx.x;
    const size_t off = (size_t)row * Cq + tid * 4;

    float4 v = *(const float4*)&in[off];
    float s = v.x + v.y + v.z + v.w;
    float ss = v.x * v.x + v.y * v.y + v.z * v.z + v.w * v.w;

#pragma unroll
    for (int o2 = 16; o2 > 0; o2 >>= 1) {
        s  += __shfl_xor_sync(0xffffffffu, s,  o2);
        ss += __shfl_xor_sync(0xffffffffu, ss, o2);
    }
    __shared__ float sh_s[8], sh_ss[8], red[2];
    if ((tid & 31) == 0) { sh_s[tid >> 5] = s; sh_ss[tid >> 5] = ss; }
    __syncthreads();
    if (tid < 32) {
        float a  = (tid < 8) ? sh_s[tid]  : 0.f;
        float a2 = (tid < 8) ? sh_ss[tid] : 0.f;
#pragma unroll
        for (int o2 = 4; o2 > 0; o2 >>= 1) {
            a  += __shfl_xor_sync(0xffffffffu, a,  o2);
            a2 += __shfl_xor_sync(0xffffffffu, a2, o2);
        }
        if (tid == 0) {
            float mean = a * (1.f / Cq);
            float var = a2 * (1.f / Cq) - mean * mean;
            red[0] = mean;
            red[1] = rsqrtf(var + EPSLN);
        }
    }
    __syncthreads();
    float mean = red[0], inv = red[1];

    float4 gv = *(const float4*)&g[tid * 4];
    float4 bv = *(const float4*)&bt[tid * 4];
    float4 rv = *(const float4*)&res[off];
    float4 o;
    o.x = rv.x + (v.x - mean) * inv * gv.x + bv.x;
    o.y = rv.y + (v.y - mean) * inv * gv.y + bv.y;
    o.z = rv.z + (v.z - mean) * inv * gv.z + bv.z;
    o.w = rv.w + (v.w - mean) * inv * gv.w + bv.w;
    *(float4*)&out[off] = o;
    if (outh) {
        uint2 ho;
        *(__half2*)&ho.x = __floats2half2_rn(o.x, o.y);
        *(__half2*)&ho.y = __floats2half2_rn(o.z, o.w);
        *(uint2*)&outh[off] = ho;
    }
}

// ---------------------------------------------------------------------------
// host launcher: fork/join multi-stream graph
// ---------------------------------------------------------------------------
extern "C" void kernel_launch(void* const* d_in, const int* in_sizes, int n_in,
                              void* d_out, int out_size)
{
    const float* x      = (const float*)d_in[0];
    const float* qkv_w  = (const float*)d_in[1];
    const float* qkv_b  = (const float*)d_in[2];
    const float* proj_w = (const float*)d_in[3];
    const float* proj_b = (const float*)d_in[4];
    const float* n1_g   = (const float*)d_in[5];
    const float* n1_b   = (const float*)d_in[6];
    const float* fc1_w  = (const float*)d_in[7];
    const float* fc1_b  = (const float*)d_in[8];
    const float* fc2_w  = (const float*)d_in[9];
    const float* fc2_b  = (const float*)d_in[10];
    const float* n2_g   = (const float*)d_in[11];
    const float* n2_b   = (const float*)d_in[12];
    float* out = (float*)d_out;

    static __half *p_xh = nullptr, *p_qkvh, *p_atth, *p_y1h, *p_h1h,
                  *p_wqkv, *p_wproj, *p_wfc1, *p_wfc2;
    static float *p_a, *p_y1, *p_h2;
    static cudaStream_t sW, sA, sB;
    static cudaEvent_t evStart, evRoot, evW, evA, evB;
    if (!p_xh) {
        cudaGetSymbolAddress((void**)&p_xh,   g_xh);
        cudaGetSymbolAddress((void**)&p_qkvh, g_qkvh);
        cudaGetSymbolAddress((void**)&p_atth, g_atth);
        cudaGetSymbolAddress((void**)&p_a,    g_a);
        cudaGetSymbolAddress((void**)&p_y1,   g_y1);
        cudaGetSymbolAddress((void**)&p_y1h,  g_y1h);
        cudaGetSymbolAddress((void**)&p_h1h,  g_h1h);
        cudaGetSymbolAddress((void**)&p_h2,   g_h2);
        cudaGetSymbolAddress((void**)&p_wqkv, g_wqkvT);
        cudaGetSymbolAddress((void**)&p_wproj, g_wprojT);
        cudaGetSymbolAddress((void**)&p_wfc1, g_wfc1T);
        cudaGetSymbolAddress((void**)&p_wfc2, g_wfc2T);
        cudaFuncSetAttribute(gemm_fp16, cudaFuncAttributeMaxDynamicSharedMemorySize, GEMM_SMEM);
        cudaFuncSetAttribute(attn_fp16, cudaFuncAttributeMaxDynamicSharedMemorySize, ATTN_SMEM);
        cudaStreamCreateWithFlags(&sW, cudaStreamNonBlocking);
        cudaStreamCreateWithFlags(&sA, cudaStreamNonBlocking);
        cudaStreamCreateWithFlags(&sB, cudaStreamNonBlocking);
        cudaEventCreateWithFlags(&evStart, cudaEventDisableTiming);
        cudaEventCreateWithFlags(&evRoot, cudaEventDisableTiming);
        cudaEventCreateWithFlags(&evW, cudaEventDisableTiming);
        cudaEventCreateWithFlags(&evA, cudaEventDisableTiming);
        cudaEventCreateWithFlags(&evB, cudaEventDisableTiming);
    }

    // ---- fork sW early: proj/fc1/fc2 weight transposes run aside ----
    cudaEventRecord(evStart, 0);
    cudaStreamWaitEvent(sW, evStart, 0);
    transpose_half<<<dim3(Cq / 32, Cq / 32), dim3(32, 8), 0, sW>>>(proj_w, p_wproj, Cq, Cq);
    transpose_half<<<dim3(4 * Cq / 32, Cq / 32), dim3(32, 8), 0, sW>>>(fc1_w, p_wfc1, Cq, 4 * Cq);
    transpose_half<<<dim3(Cq / 32, 4 * Cq / 32), dim3(32, 8), 0, sW>>>(fc2_w, p_wfc2, 4 * Cq, Cq);
    cudaEventRecord(evW, sW);

    // ---- critical prepass on origin stream: x->half, qkv_w transpose ----
    to_half<<<Mrows * Cq / 2048, 256>>>(x, p_xh);
    transpose_half<<<dim3(3 * Cq / 32, Cq / 32), dim3(32, 8)>>>(qkv_w, p_wqkv, Cq, 3 * Cq);
    cudaEventRecord(evRoot, 0);
    cudaStreamWaitEvent(sA, evRoot, 0);
    cudaStreamWaitEvent(sB, evRoot, 0);

    // ---- per-half chains on sA / sB (halves = batches 0-3 / 4-7) ----
    for (int half = 0; half < 2; half++) {
        cudaStream_t st = half ? sB : sA;
        const size_t m = (size_t)half * MHALF;
        const __half* xh  = p_xh  + m * Cq;
        __half* qkvh      = p_qkvh + m * 3 * Cq;
        __half* atth      = p_atth + m * Cq;
        float*  a_        = p_a    + m * Cq;
        float*  y1_       = p_y1   + m * Cq;
        __half* y1h_      = p_y1h  + m * Cq;
        __half* h1h_      = p_h1h  + m * 4 * Cq;
        float*  h2_       = p_h2   + m * Cq;
        float*  out_      = out    + m * Cq;

        // qkv
        gemm_fp16<<<dim3(3 * Cq / 128, MHALF / 128), 256, GEMM_SMEM, st>>>(
            xh, p_wqkv, qkv_b, nullptr, qkvh, 3 * Cq, Cq, 0);
        // attention (4 batches x 16 heads)
        attn_fp16<<<dim3(Nq / 64, (Bq / 2) * 16), 128, ATTN_SMEM, st>>>(qkvh, atth);
        // proj (needs transposed proj_w)
        cudaStreamWaitEvent(st, evW, 0);
        gemm_fp16<<<dim3(Cq / 128, MHALF / 128), 256, GEMM_SMEM, st>>>(
            atth, p_wproj, proj_b, a_, nullptr, Cq, Cq, 0);
        // y1 = a + LN(a)
        ln_add_kernel<<<MHALF, 256, 0, st>>>(a_, a_, n1_g, n1_b, y1_, y1h_);
        // fc1
        gemm_fp16<<<dim3(4 * Cq / 128, MHALF / 128), 256, GEMM_SMEM, st>>>(
            y1h_, p_wfc1, fc1_b, nullptr, h1h_, 4 * Cq, Cq, 1);
        // fc2
        gemm_fp16<<<dim3(Cq / 128, MHALF / 128), 256, GEMM_SMEM, st>>>(
            h1h_, p_wfc2, fc2_b, h2_, nullptr, Cq, 4 * Cq, 0);
        // out = y1 + LN(h2)
        ln_add_kernel<<<MHALF, 256, 0, st>>>(h2_, y1_, n2_g, n2_b, out_, nullptr);
    }

    // ---- join back to origin stream ----
    cudaEventRecord(evA, sA);
    cudaEventRecord(evB, sB);
    cudaStreamWaitEvent(0, evA, 0);
    cudaStreamWaitEvent(0, evB, 0);
}

// round 10
// speedup vs baseline: 6.3218x; 1.0056x over previous
#include <cuda_runtime.h>
#include <cuda_fp16.h>
#include <math.h>
#include <stdint.h>

// ---------------------------------------------------------------------------
// ViT block, all matmul on mma.sync fp16 (fp32 accumulate).
// Four batch-quarters pipelined across origin + 3 created streams (resource
// footprint identical to the proven round-8 config: 3 streams; 7 light events).
//   qkv = x @ qkv_w + qkv_b            (gemm_fp16 -> half)
//   flash-attention per (b,h)          (attn_fp16)
//   a  = att @ proj_w + proj_b         (gemm_fp16 -> fp32)
//   y1 = a + LN(a; n1)                 (ln_add -> fp32 + half)
//   h1 = GELU(y1 @ fc1_w + fc1_b)      (gemm_fp16 -> half)
//   h2 = h1 @ fc2_w + fc2_b            (gemm_fp16 -> fp32)
//   out = y1 + LN(h2; n2)              (ln_add -> fp32)
// ---------------------------------------------------------------------------

#define Bq   8
#define Nq   1024
#define Cq   1024
#define Mrows (Bq*Nq)          // 8192
#define NCHUNK 4
#define MCHUNK (Mrows/NCHUNK)  // 2048 rows (2 batches) per chain
#define EPSLN 1e-6f

// Scratch (static device memory)
__device__ __half g_xh  [Mrows * Cq];
__device__ __half g_qkvh[Mrows * 3 * Cq];
__device__ __half g_atth[Mrows * Cq];
__device__ float  g_a   [Mrows * Cq];
__device__ float  g_y1  [Mrows * Cq];
__device__ __half g_y1h [Mrows * Cq];
__device__ __half g_h1h [Mrows * 4 * Cq];
__device__ float  g_h2  [Mrows * Cq];
__device__ __half g_wqkvT[3 * Cq * Cq];
__device__ __half g_wprojT[Cq * Cq];
__device__ __half g_wfc1T[4 * Cq * Cq];
__device__ __half g_wfc2T[Cq * 4 * Cq];

__device__ __forceinline__ uint32_t smem_u32(const void* p) {
    uint32_t a;
    asm("{ .reg .u64 t; cvta.to.shared.u64 t, %1; cvt.u32.u64 %0, t; }" : "=r"(a) : "l"(p));
    return a;
}

#define MMA_F16(d, a, b)                                                   \
    asm volatile(                                                          \
        "mma.sync.aligned.m16n8k16.row.col.f32.f16.f16.f32 "               \
        "{%0,%1,%2,%3}, {%4,%5,%6,%7}, {%8,%9}, {%0,%1,%2,%3};"            \
        : "+f"(d[0]), "+f"(d[1]), "+f"(d[2]), "+f"(d[3])                   \
        : "r"(a[0]), "r"(a[1]), "r"(a[2]), "r"(a[3]), "r"(b[0]), "r"(b[1]))

#define LDSM_X4(r0, r1, r2, r3, addr)                                      \
    asm volatile("ldmatrix.sync.aligned.m8n8.x4.shared.b16 {%0,%1,%2,%3}, [%4];" \
                 : "=r"(r0), "=r"(r1), "=r"(r2), "=r"(r3) : "r"(addr))

#define CP_ASYNC16(dst, src) \
    asm volatile("cp.async.cg.shared.global [%0], [%1], 16;" :: "r"(dst), "l"(src))
#define CP_COMMIT() asm volatile("cp.async.commit_group;" ::: "memory")
#define CP_WAIT(n)  asm volatile("cp.async.wait_group %0;" :: "n"(n) : "memory")

extern __shared__ __align__(16) char g_dynsmem[];

// ---------------------------------------------------------------------------
// fp16 mma GEMM: C[M,N] = A[M,K] @ Bt[N,K]^T + bias (+GELU).
// 128x128 tile, BK=32, 4-stage cp.async, 256 threads (8 warps, 64x32 tiles).
// Fragments via ldmatrix.x4. Stage: A 128x40h + B 128x40h = 20480 B.
// ---------------------------------------------------------------------------
#define GEMM_SMEM 81920

__global__ __launch_bounds__(256, 2) void gemm_fp16(
    const __half* __restrict__ A, const __half* __restrict__ Bt,
    const float* __restrict__ bias, float* __restrict__ Cf,
    __half* __restrict__ Ch, int N, int K, int gelu)
{
    const uint32_t smu = smem_u32(g_dynsmem);

    const int tid  = threadIdx.x;
    const int lane = tid & 31;
    const int warp = tid >> 5;
    const int gid  = lane >> 2;
    const int tig  = lane & 3;
    const int wm   = (warp >> 2) * 64;
    const int wn   = (warp & 3) * 32;
    const int bm   = blockIdx.y * 128;
    const int bn   = blockIdx.x * 128;

    const int c1 = tid + 256;
    const int r0 = tid >> 2, q0c = (tid & 3);
    const int r1 = c1 >> 2,  q1c = (c1 & 3);

    const int lrowA = ((lane >> 3) & 1) * 8 + (lane & 7);
    const int lcolA = (lane >> 4) * 8;
    const int lrowB = ((lane >> 4) & 1) * 8 + (lane & 7);
    const int lcolB = ((lane >> 3) & 1) * 8;
    const uint32_t aoff = (uint32_t)(((wm + lrowA) * 40 + lcolA) * 2);
    const uint32_t boff = (uint32_t)(10240 + ((wn + lrowB) * 40 + lcolB) * 2);

    float acc[4][4][4];
#pragma unroll
    for (int mt = 0; mt < 4; mt++)
#pragma unroll
        for (int nt = 0; nt < 4; nt++)
#pragma unroll
            for (int r = 0; r < 4; r++) acc[mt][nt][r] = 0.f;

    const int T = K >> 5;

#define GEMM_ISSUE(t)                                                            \
    do {                                                                         \
        const uint32_t sb_ = smu + (uint32_t)(((t) & 3) * 20480);                \
        CP_ASYNC16(sb_ + r0 * 80 + q0c * 16, &A[(size_t)(bm + r0) * K + (t) * 32 + q0c * 8]); \
        CP_ASYNC16(sb_ + r1 * 80 + q1c * 16, &A[(size_t)(bm + r1) * K + (t) * 32 + q1c * 8]); \
        CP_ASYNC16(sb_ + 10240 + r0 * 80 + q0c * 16, &Bt[(size_t)(bn + r0) * K + (t) * 32 + q0c * 8]); \
        CP_ASYNC16(sb_ + 10240 + r1 * 80 + q1c * 16, &Bt[(size_t)(bn + r1) * K + (t) * 32 + q1c * 8]); \
        CP_COMMIT();                                                             \
    } while (0)

    GEMM_ISSUE(0); GEMM_ISSUE(1); GEMM_ISSUE(2);

    for (int t = 0; t < T; t++) {
        if (t < T - 2)      { CP_WAIT(2); }
        else if (t == T - 2){ CP_WAIT(1); }
        else                { CP_WAIT(0); }
        __syncthreads();
        if (t + 3 < T) GEMM_ISSUE(t + 3);

        const uint32_t sb = smu + (uint32_t)((t & 3) * 20480);
#pragma unroll
        for (int ks = 0; ks < 2; ks++) {
            uint32_t afr[4][4], bfr[4][2];
#pragma unroll
            for (int mt = 0; mt < 4; mt++)
                LDSM_X4(afr[mt][0], afr[mt][1], afr[mt][2], afr[mt][3],
                        sb + aoff + (uint32_t)(mt * 1280 + ks * 32));
#pragma unroll
            for (int ntp = 0; ntp < 2; ntp++)
                LDSM_X4(bfr[2 * ntp][0], bfr[2 * ntp][1],
                        bfr[2 * ntp + 1][0], bfr[2 * ntp + 1][1],
                        sb + boff + (uint32_t)(ntp * 1280 + ks * 32));
#pragma unroll
            for (int mt = 0; mt < 4; mt++)
#pragma unroll
                for (int nt = 0; nt < 4; nt++)
                    MMA_F16(acc[mt][nt], afr[mt], bfr[nt]);
        }
    }
#undef GEMM_ISSUE

#pragma unroll
    for (int mt = 0; mt < 4; mt++) {
        const int row0 = bm + wm + mt * 16 + gid;
#pragma unroll
        for (int nt = 0; nt < 4; nt++) {
            const int col = bn + wn + nt * 8 + tig * 2;
            float2 bv = *(const float2*)&bias[col];
            float c0 = acc[mt][nt][0] + bv.x;
            float c1 = acc[mt][nt][1] + bv.y;
            float c2 = acc[mt][nt][2] + bv.x;
            float c3 = acc[mt][nt][3] + bv.y;
            if (gelu) {
                c0 = 0.5f * c0 * (1.f + erff(c0 * 0.70710678118654752f));
                c1 = 0.5f * c1 * (1.f + erff(c1 * 0.70710678118654752f));
                c2 = 0.5f * c2 * (1.f + erff(c2 * 0.70710678118654752f));
                c3 = 0.5f * c3 * (1.f + erff(c3 * 0.70710678118654752f));
            }
            if (Cf) {
                float2 o01; o01.x = c0; o01.y = c1;
                float2 o23; o23.x = c2; o23.y = c3;
                *(float2*)&Cf[(size_t)row0 * N + col] = o01;
                *(float2*)&Cf[(size_t)(row0 + 8) * N + col] = o23;
            }
            if (Ch) {
                *(__half2*)&Ch[(size_t)row0 * N + col] = __floats2half2_rn(c0, c1);
                *(__half2*)&Ch[(size_t)(row0 + 8) * N + col] = __floats2half2_rn(c2, c3);
            }
        }
    }
}

// ---------------------------------------------------------------------------
// Flash attention, fp16 mma, cp.async double-buffered K/V, ldmatrix frags.
// grid (Nq/64, nbatch*H), 128 threads (4 warps, 16 q-rows each).
// ---------------------------------------------------------------------------
#define AS_H 72
#define ATTN_SMEM (5 * 64 * AS_H * 2)

__global__ __launch_bounds__(128, 4) void attn_fp16(
    const __half* __restrict__ qkv, __half* __restrict__ out)
{
    __half* Qs = (__half*)g_dynsmem;
    const uint32_t qbase = smem_u32(Qs);
    const uint32_t kbase0 = qbase + 64 * AS_H * 2;
    const uint32_t vbase0 = qbase + 3 * 64 * AS_H * 2;

    const int bh = blockIdx.y;
    const int b = bh >> 4;
    const int h = bh & 15;
    const int q0 = blockIdx.x * 64;
    const int tid = threadIdx.x;
    const int wid = tid >> 5;
    const int lane = tid & 31;
    const int gid = lane >> 2;
    const int tig = lane & 3;
    const int row0 = wid * 16 + gid;

    const size_t base = (size_t)b * Nq * (3 * Cq);
    const __half2 sc2 = __float2half2_rn(0.125f);

    const int lrowA = ((lane >> 3) & 1) * 8 + (lane & 7);
    const int lcolA = (lane >> 4) * 8;
    const int lrowB = ((lane >> 4) & 1) * 8 + (lane & 7);
    const int lcolB = ((lane >> 3) & 1) * 8;
    const uint32_t qoff = (uint32_t)(((wid * 16 + lrowA) * AS_H + lcolA) * 2);
    const uint32_t koff = (uint32_t)((lrowB * AS_H + lcolB) * 2);

    const int cr = tid >> 3;
    const int cc8 = tid & 7;

#pragma unroll
    for (int i = 0; i < 4; i++) {
        int idx = tid + i * 128;
        int r = idx >> 3;
        int c8 = idx & 7;
        uint4 v = *(const uint4*)&qkv[base + (size_t)(q0 + r) * (3 * Cq) + h * 64 + c8 * 8];
        __half2* hv = (__half2*)&v;
        hv[0] = __hmul2(hv[0], sc2);
        hv[1] = __hmul2(hv[1], sc2);
        hv[2] = __hmul2(hv[2], sc2);
        hv[3] = __hmul2(hv[3], sc2);
        *(uint4*)&Qs[r * AS_H + c8 * 8] = v;
    }

#define ATTN_ISSUE(t)                                                            \
    do {                                                                         \
        const uint32_t kb_ = kbase0 + (uint32_t)(((t) & 1) * 64 * AS_H * 2);     \
        const uint32_t vb_ = vbase0 + (uint32_t)(((t) & 1) * 64 * AS_H * 2);     \
        _Pragma("unroll")                                                        \
        for (int i_ = 0; i_ < 4; i_++) {                                         \
            const int r_ = cr + i_ * 16;                                         \
            const size_t src_ = base + (size_t)((t) * 64 + r_) * (3 * Cq) + h * 64 + cc8 * 8; \
            CP_ASYNC16(kb_ + (r_ * AS_H + cc8 * 8) * 2, &qkv[src_ + Cq]);        \
            CP_ASYNC16(vb_ + (r_ * AS_H + cc8 * 8) * 2, &qkv[src_ + 2 * Cq]);    \
        }                                                                        \
        CP_COMMIT();                                                             \
    } while (0)

    ATTN_ISSUE(0);
    __syncthreads();

    uint32_t qf[4][4];
#pragma unroll
    for (int ks = 0; ks < 4; ks++)
        LDSM_X4(qf[ks][0], qf[ks][1], qf[ks][2], qf[ks][3], qbase + qoff + ks * 32);

    float of[8][4];
#pragma unroll
    for (int nt = 0; nt < 8; nt++)
#pragma unroll
        for (int r = 0; r < 4; r++) of[nt][r] = 0.f;
    float m0 = -INFINITY, m1 = -INFINITY, l0 = 0.f, l1 = 0.f;

    const int TT = Nq / 64;
    for (int t = 0; t < TT; t++) {
        CP_WAIT(0);
        __syncthreads();
        if (t + 1 < TT) ATTN_ISSUE(t + 1);

        const uint32_t kb = kbase0 + (uint32_t)((t & 1) * 64 * AS_H * 2);
        const uint32_t vb = vbase0 + (uint32_t)((t & 1) * 64 * AS_H * 2);

        float sf[8][4];
#pragma unroll
        for (int nt = 0; nt < 8; nt++)
#pragma unroll
            for (int r = 0; r < 4; r++) sf[nt][r] = 0.f;
#pragma unroll
        for (int ks = 0; ks < 4; ks++) {
#pragma unroll
            for (int ntp = 0; ntp < 4; ntp++) {
                uint32_t b0, b1, b2, b3;
                LDSM_X4(b0, b1, b2, b3, kb + koff + (uint32_t)(ntp * 16 * AS_H * 2 + ks * 32));
                uint32_t f0[2] = {b0, b1};
                uint32_t f1[2] = {b2, b3};
                MMA_F16(sf[2 * ntp], qf[ks], f0);
                MMA_F16(sf[2 * ntp + 1], qf[ks], f1);
            }
        }

        float mx0 = -INFINITY, mx1 = -INFINITY;
#pragma unroll
        for (int nt = 0; nt < 8; nt++) {
            mx0 = fmaxf(mx0, fmaxf(sf[nt][0], sf[nt][1]));
            mx1 = fmaxf(mx1, fmaxf(sf[nt][2], sf[nt][3]));
        }
        mx0 = fmaxf(mx0, __shfl_xor_sync(0xffffffffu, mx0, 1));
        mx0 = fmaxf(mx0, __shfl_xor_sync(0xffffffffu, mx0, 2));
        mx1 = fmaxf(mx1, __shfl_xor_sync(0xffffffffu, mx1, 1));
        mx1 = fmaxf(mx1, __shfl_xor_sync(0xffffffffu, mx1, 2));
        const float mn0 = fmaxf(m0, mx0);
        const float mn1 = fmaxf(m1, mx1);
        const float cr0 = __expf(m0 - mn0);
        const float cr1 = __expf(m1 - mn1);
        float rs0 = 0.f, rs1 = 0.f;
#pragma unroll
        for (int nt = 0; nt < 8; nt++) {
            float p0 = __expf(sf[nt][0] - mn0);
            float p1 = __expf(sf[nt][1] - mn0);
            float p2 = __expf(sf[nt][2] - mn1);
            float p3 = __expf(sf[nt][3] - mn1);
            rs0 += p0 + p1;
            rs1 += p2 + p3;
            *(__half2*)&Qs[row0 * AS_H + nt * 8 + tig * 2] = __floats2half2_rn(p0, p1);
            *(__half2*)&Qs[(row0 + 8) * AS_H + nt * 8 + tig * 2] = __floats2half2_rn(p2, p3);
            of[nt][0] *= cr0; of[nt][1] *= cr0;
            of[nt][2] *= cr1; of[nt][3] *= cr1;
        }
        rs0 += __shfl_xor_sync(0xffffffffu, rs0, 1);
        rs0 += __shfl_xor_sync(0xffffffffu, rs0, 2);
        rs1 += __shfl_xor_sync(0xffffffffu, rs1, 1);
        rs1 += __shfl_xor_sync(0xffffffffu, rs1, 2);
        m0 = mn0; m1 = mn1;
        l0 = l0 * cr0 + rs0;
        l1 = l1 * cr1 + rs1;
        __syncwarp();

        const int rl = lane & 15;
#pragma unroll
        for (int ks = 0; ks < 4; ks++) {
            uint32_t pf[4];
            LDSM_X4(pf[0], pf[1], pf[2], pf[3], qbase + qoff + (uint32_t)(ks * 32));
#pragma unroll
            for (int nt = 0; nt < 8; nt++) {
                uint32_t b0, b1;
                uint32_t addr = vb + (uint32_t)(((ks * 16 + rl) * AS_H + nt * 8) * 2);
                asm volatile(
                    "ldmatrix.sync.aligned.m8n8.x2.trans.shared.b16 {%0,%1}, [%2];"
                    : "=r"(b0), "=r"(b1) : "r"(addr));
                uint32_t bfr[2] = {b0, b1};
                MMA_F16(of[nt], pf, bfr);
            }
        }
        __syncwarp();
    }
#undef ATTN_ISSUE

    const float inv0 = 1.f / l0;
    const float inv1 = 1.f / l1;
    const size_t grow0 = (size_t)b * Nq + q0 + row0;
#pragma unroll
    for (int nt = 0; nt < 8; nt++) {
        const int col = h * 64 + nt * 8 + tig * 2;
        *(__half2*)&out[grow0 * Cq + col] =
            __floats2half2_rn(of[nt][0] * inv0, of[nt][1] * inv0);
        *(__half2*)&out[(grow0 + 8) * Cq + col] =
            __floats2half2_rn(of[nt][2] * inv1, of[nt][3] * inv1);
    }
}

// ---------------------------------------------------------------------------
// fp32 -> half copy (8 elems/thread)
// ---------------------------------------------------------------------------
__global__ __launch_bounds__(256) void to_half(
    const float* __restrict__ in, __half* __restrict__ out)
{
    const size_t i = ((size_t)blockIdx.x * 256 + threadIdx.x) * 8;
    float4 v0 = *(const float4*)&in[i];
    float4 v1 = *(const float4*)&in[i + 4];
    uint4 o;
    *(__half2*)&o.x = __floats2half2_rn(v0.x, v0.y);
    *(__half2*)&o.y = __floats2half2_rn(v0.z, v0.w);
    *(__half2*)&o.z = __floats2half2_rn(v1.x, v1.y);
    *(__half2*)&o.w = __floats2half2_rn(v1.z, v1.w);
    *(uint4*)&out[i] = o;
}

// ---------------------------------------------------------------------------
// transpose + fp16 convert: out[n][k] = half(in[k][n])
// ---------------------------------------------------------------------------
__global__ __launch_bounds__(256) void transpose_half(
    const float* __restrict__ in, __half* __restrict__ out, int K, int N)
{
    __shared__ float t[32][33];
    const int n0 = blockIdx.x * 32, k0 = blockIdx.y * 32;
    const int tx = threadIdx.x, ty = threadIdx.y;
#pragma unroll
    for (int i = 0; i < 4; i++)
        t[ty + i * 8][tx] = in[(size_t)(k0 + ty + i * 8) * N + n0 + tx];
    __syncthreads();
#pragma unroll
    for (int i = 0; i < 4; i++)
        out[(size_t)(n0 + ty + i * 8) * K + k0 + tx] = __float2half_rn(t[tx][ty + i * 8]);
}

// ---------------------------------------------------------------------------
// out = res + LayerNorm(in)*g + b ; optional half copy of out
// ---------------------------------------------------------------------------
__global__ __launch_bounds__(256) void ln_add_kernel(
    const float* __restrict__ in, const float* __restrict__ res,
    const float* __restrict__ g, const float* __restrict__ bt,
    float* __restrict__ out, __half* __restrict__ outh)
{
    const int row = blockIdx.x;
    const int tid = threadIdx.x;
    const size_t off = (size_t)row * Cq + tid * 4;

    float4 v = *(const float4*)&in[off];
    float s = v.x + v.y + v.z + v.w;
    float ss = v.x * v.x + v.y * v.y + v.z * v.z + v.w * v.w;

#pragma unroll
    for (int o2 = 16; o2 > 0; o2 >>= 1) {
        s  += __shfl_xor_sync(0xffffffffu, s,  o2);
        ss += __shfl_xor_sync(0xffffffffu, ss, o2);
    }
    __shared__ float sh_s[8], sh_ss[8], red[2];
    if ((tid & 31) == 0) { sh_s[tid >> 5] = s; sh_ss[tid >> 5] = ss; }
    __syncthreads();
    if (tid < 32) {
        float a  = (tid < 8) ? sh_s[tid]  : 0.f;
        float a2 = (tid < 8) ? sh_ss[tid] : 0.f;
#pragma unroll
        for (int o2 = 4; o2 > 0; o2 >>= 1) {
            a  += __shfl_xor_sync(0xffffffffu, a,  o2);
            a2 += __shfl_xor_sync(0xffffffffu, a2, o2);
        }
        if (tid == 0) {
            float mean = a * (1.f / Cq);
            float var = a2 * (1.f / Cq) - mean * mean;
            red[0] = mean;
            red[1] = rsqrtf(var + EPSLN);
        }
    }
    __syncthreads();
    float mean = red[0], inv = red[1];

    float4 gv = *(const float4*)&g[tid * 4];
    float4 bv = *(const float4*)&bt[tid * 4];
    float4 rv = *(const float4*)&res[off];
    float4 o;
    o.x = rv.x + (v.x - mean) * inv * gv.x + bv.x;
    o.y = rv.y + (v.y - mean) * inv * gv.y + bv.y;
    o.z = rv.z + (v.z - mean) * inv * gv.z + bv.z;
    o.w = rv.w + (v.w - mean) * inv * gv.w + bv.w;
    *(float4*)&out[off] = o;
    if (outh) {
        uint2 ho;
        *(__half2*)&ho.x = __floats2half2_rn(o.x, o.y);
        *(__half2*)&ho.y = __floats2half2_rn(o.z, o.w);
        *(uint2*)&outh[off] = ho;
    }
}

// ---------------------------------------------------------------------------
// host launcher: 4 quarter-chains over origin + 3 streams (round-8 footprint)
// ---------------------------------------------------------------------------
extern "C" void kernel_launch(void* const* d_in, const int* in_sizes, int n_in,
                              void* d_out, int out_size)
{
    const float* x      = (const float*)d_in[0];
    const float* qkv_w  = (const float*)d_in[1];
    const float* qkv_b  = (const float*)d_in[2];
    const float* proj_w = (const float*)d_in[3];
    const float* proj_b = (const float*)d_in[4];
    const float* n1_g   = (const float*)d_in[5];
    const float* n1_b   = (const float*)d_in[6];
    const float* fc1_w  = (const float*)d_in[7];
    const float* fc1_b  = (const float*)d_in[8];
    const float* fc2_w  = (const float*)d_in[9];
    const float* fc2_b  = (const float*)d_in[10];
    const float* n2_g   = (const float*)d_in[11];
    const float* n2_b   = (const float*)d_in[12];
    float* out = (float*)d_out;

    static __half *p_xh = nullptr, *p_qkvh, *p_atth, *p_y1h, *p_h1h,
                  *p_wqkv, *p_wproj, *p_wfc1, *p_wfc2;
    static float *p_a, *p_y1, *p_h2;
    static cudaStream_t sW, sA, sB;
    static cudaEvent_t evStart, evRoot, evX, evW, evA, evB, evC;
    if (!p_xh) {
        cudaGetSymbolAddress((void**)&p_xh,   g_xh);
        cudaGetSymbolAddress((void**)&p_qkvh, g_qkvh);
        cudaGetSymbolAddress((void**)&p_atth, g_atth);
        cudaGetSymbolAddress((void**)&p_a,    g_a);
        cudaGetSymbolAddress((void**)&p_y1,   g_y1);
        cudaGetSymbolAddress((void**)&p_y1h,  g_y1h);
        cudaGetSymbolAddress((void**)&p_h1h,  g_h1h);
        cudaGetSymbolAddress((void**)&p_h2,   g_h2);
        cudaGetSymbolAddress((void**)&p_wqkv, g_wqkvT);
        cudaGetSymbolAddress((void**)&p_wproj, g_wprojT);
        cudaGetSymbolAddress((void**)&p_wfc1, g_wfc1T);
        cudaGetSymbolAddress((void**)&p_wfc2, g_wfc2T);
        cudaFuncSetAttribute(gemm_fp16, cudaFuncAttributeMaxDynamicSharedMemorySize, GEMM_SMEM);
        cudaFuncSetAttribute(attn_fp16, cudaFuncAttributeMaxDynamicSharedMemorySize, ATTN_SMEM);
        cudaStreamCreateWithFlags(&sW, cudaStreamNonBlocking);
        cudaStreamCreateWithFlags(&sA, cudaStreamNonBlocking);
        cudaStreamCreateWithFlags(&sB, cudaStreamNonBlocking);
        cudaEventCreateWithFlags(&evStart, cudaEventDisableTiming);
        cudaEventCreateWithFlags(&evRoot, cudaEventDisableTiming);
        cudaEventCreateWithFlags(&evX, cudaEventDisableTiming);
        cudaEventCreateWithFlags(&evW, cudaEventDisableTiming);
        cudaEventCreateWithFlags(&evA, cudaEventDisableTiming);
        cudaEventCreateWithFlags(&evB, cudaEventDisableTiming);
        cudaEventCreateWithFlags(&evC, cudaEventDisableTiming);
    }

    // ---- fork ----
    cudaEventRecord(evStart, 0);
    cudaStreamWaitEvent(sW, evStart, 0);
    cudaStreamWaitEvent(sA, evStart, 0);
    cudaStreamWaitEvent(sB, evStart, 0);

    // sW: proj/fc1/fc2 weight transposes (then hosts quarter 3)
    transpose_half<<<dim3(Cq / 32, Cq / 32), dim3(32, 8), 0, sW>>>(proj_w, p_wproj, Cq, Cq);
    transpose_half<<<dim3(4 * Cq / 32, Cq / 32), dim3(32, 8), 0, sW>>>(fc1_w, p_wfc1, Cq, 4 * Cq);
    transpose_half<<<dim3(Cq / 32, 4 * Cq / 32), dim3(32, 8), 0, sW>>>(fc2_w, p_wfc2, 4 * Cq, Cq);
    cudaEventRecord(evW, sW);

    // sA: x -> half (then hosts quarter 1)
    to_half<<<Mrows * Cq / 2048, 256, 0, sA>>>(x, p_xh);
    cudaEventRecord(evX, sA);

    // origin: qkv_w transpose (then hosts quarter 0)
    transpose_half<<<dim3(3 * Cq / 32, Cq / 32), dim3(32, 8)>>>(qkv_w, p_wqkv, Cq, 3 * Cq);
    cudaEventRecord(evRoot, 0);

    // chain streams: q0=origin, q1=sA, q2=sB, q3=sW
    cudaStream_t chain[NCHUNK] = {(cudaStream_t)0, sA, sB, sW};

    // dependencies to start each chain:
    cudaStreamWaitEvent(0, evX, 0);            // q0 needs x->half (qkv_w local)
    cudaStreamWaitEvent(sA, evRoot, 0);        // q1 needs qkv_w (x->half local)
    cudaStreamWaitEvent(sB, evRoot, 0);        // q2 needs both
    cudaStreamWaitEvent(sB, evX, 0);
    cudaStreamWaitEvent(sW, evRoot, 0);        // q3 needs both (transposes local)
    cudaStreamWaitEvent(sW, evX, 0);

    for (int q = 0; q < NCHUNK; q++) {
        cudaStream_t st = chain[q];
        const size_t m = (size_t)q * MCHUNK;
        const __half* xh  = p_xh  + m * Cq;
        __half* qkvh      = p_qkvh + m * 3 * Cq;
        __half* atth      = p_atth + m * Cq;
        float*  a_        = p_a    + m * Cq;
        float*  y1_       = p_y1   + m * Cq;
        __half* y1h_      = p_y1h  + m * Cq;
        __half* h1h_      = p_h1h  + m * 4 * Cq;
        float*  h2_       = p_h2   + m * Cq;
        float*  out_      = out    + m * Cq;

        // qkv
        gemm_fp16<<<dim3(3 * Cq / 128, MCHUNK / 128), 256, GEMM_SMEM, st>>>(
            xh, p_wqkv, qkv_b, nullptr, qkvh, 3 * Cq, Cq, 0);
        // attention (2 batches x 16 heads)
        attn_fp16<<<dim3(Nq / 64, (Bq / NCHUNK) * 16), 128, ATTN_SMEM, st>>>(qkvh, atth);
        // proj (needs transposed proj_w; q3 is on sW so already ordered)
        if (st != sW) cudaStreamWaitEvent(st, evW, 0);
        gemm_fp16<<<dim3(Cq / 128, MCHUNK / 128), 256, GEMM_SMEM, st>>>(
            atth, p_wproj, proj_b, a_, nullptr, Cq, Cq, 0);
        // y1 = a + LN(a)
        ln_add_kernel<<<MCHUNK, 256, 0, st>>>(a_, a_, n1_g, n1_b, y1_, y1h_);
        // fc1
        gemm_fp16<<<dim3(4 * Cq / 128, MCHUNK / 128), 256, GEMM_SMEM, st>>>(
            y1h_, p_wfc1, fc1_b, nullptr, h1h_, 4 * Cq, Cq, 1);
        // fc2
        gemm_fp16<<<dim3(Cq / 128, MCHUNK / 128), 256, GEMM_SMEM, st>>>(
            h1h_, p_wfc2, fc2_b, h2_, nullptr, Cq, 4 * Cq, 0);
        // out = y1 + LN(h2)
        ln_add_kernel<<<MCHUNK, 256, 0, st>>>(h2_, y1_, n2_g, n2_b, out_, nullptr);
    }

    // ---- join non-origin chains back to origin ----
    cudaEventRecord(evA, sA);
    cudaEventRecord(evB, sB);
    cudaEventRecord(evC, sW);
    cudaStreamWaitEvent(0, evA, 0);
    cudaStreamWaitEvent(0, evB, 0);
    cudaStreamWaitEvent(0, evC, 0);
}